// round 13
// baseline (speedup 1.0000x reference)
#include <cuda_runtime.h>
#include <cuda_fp16.h>
#include <math.h>
#include <stdint.h>

// Problem constants
#define BATCH 4
#define SEQ   2048
#define CMODEL 1024
#define NHEAD 16
#define HDIM  64
#define BH    (BATCH*NHEAD)          // 64
#define MROWS (BATCH*SEQ)            // 8192

// Scratch (allocation-free rule: __device__ globals)
__device__ __half g_Q[(size_t)BH*SEQ*HDIM];    // [bh][t][d], pre-scaled by 1/8
__device__ __half g_K[(size_t)BH*SEQ*HDIM];    // [bh][t][d]
__device__ __half g_Vt[(size_t)BH*HDIM*SEQ];   // [bh][d][t]  (transposed)
__device__ __half g_A[(size_t)MROWS*CMODEL];   // attention out (proj input)
__device__ __half g_Xh[(size_t)MROWS*CMODEL];      // x in fp16
__device__ __half g_Wh[(size_t)3*CMODEL*CMODEL];   // qkv_w in fp16
__device__ __half g_Woh[(size_t)CMODEL*CMODEL];    // out_w in fp16

// log2(10000)/64
#define ROPE_L2 0.20762050593060493f

#define KPAD 40    // GEMM: halves per smem row (32 used + 8 pad); 80B row, 16B-aligned
#define KSPAD 72   // attn K tile: 64 + 8 -> 144B row
#define VSPAD 40   // attn V tile: 32 + 8 -> 80B row

__device__ __forceinline__ void cp16(void* s, const void* g) {
    uint32_t sa = (uint32_t)__cvta_generic_to_shared(s);
    asm volatile("cp.async.cg.shared.global [%0], [%1], 16;\n" :: "r"(sa), "l"(g));
}
#define CP_COMMIT asm volatile("cp.async.commit_group;\n" ::: "memory")
#define CP_WAIT0  asm volatile("cp.async.wait_group 0;\n" ::: "memory")
#define CP_WAIT1  asm volatile("cp.async.wait_group 1;\n" ::: "memory")

#define U32(p) (*(const uint32_t*)(p))

__device__ __forceinline__ uint32_t smem_u32(const void* p) {
    return (uint32_t)__cvta_generic_to_shared(p);
}

__device__ __forceinline__ uint32_t packh2(float lo, float hi) {
    __half2 h = __floats2half2_rn(lo, hi);
    return *(uint32_t*)&h;
}

__device__ __forceinline__ void mma_f16(float4& d, const uint32_t* a, const uint32_t* b) {
    asm volatile(
        "mma.sync.aligned.m16n8k16.row.col.f32.f16.f16.f32 "
        "{%0,%1,%2,%3}, {%4,%5,%6,%7}, {%8,%9}, {%0,%1,%2,%3};\n"
        : "+f"(d.x), "+f"(d.y), "+f"(d.z), "+f"(d.w)
        : "r"(a[0]), "r"(a[1]), "r"(a[2]), "r"(a[3]), "r"(b[0]), "r"(b[1]));
}

#define LDSM4(R, ADDR) \
    asm volatile("ldmatrix.sync.aligned.m8n8.x4.shared.b16 {%0,%1,%2,%3}, [%4];" \
        : "=r"((R)[0]), "=r"((R)[1]), "=r"((R)[2]), "=r"((R)[3]) : "r"(ADDR))

// ---------------------------------------------------------------------------
// Kernel 0: fp32 -> fp16 convert (vectorized)
// ---------------------------------------------------------------------------
__global__ __launch_bounds__(256) void cvt_half_kernel(
    const float4* __restrict__ in, uint2* __restrict__ outp, int n4)
{
    const int i = blockIdx.x * 256 + threadIdx.x;
    if (i < n4) {
        float4 v = in[i];
        uint2 o;
        o.x = packh2(v.x, v.y);
        o.y = packh2(v.z, v.w);
        outp[i] = o;
    }
}

// ---------------------------------------------------------------------------
// GEMM mainloop: C[64x128] tile of A[M][1024](half) * B[N][1024](half)^T.
// 256 threads, 8 warps in 2(M) x 4(N); warp tile 32x32 (acc = 32 regs).
// Same 2-stage cp.async skeleton as R12; ldmatrix fragment loads.
// Occupancy target: 3 CTAs/SM (launch_bounds cap).
// ---------------------------------------------------------------------------
#define AS_BUF_BYTES (64 * KPAD * 2)    // 5120
#define BS_BUF_BYTES (128 * KPAD * 2)   // 10240
#define GEMM_MAINLOOP(APTR, BPTR)                                                   \
    __shared__ __half As[2][64][KPAD];                                              \
    __shared__ __half Bs[2][128][KPAD];                                             \
    const int tid = threadIdx.x;                                                    \
    const int w = tid >> 5, lane = tid & 31, g = lane >> 2, tg = lane & 3;          \
    const int wm = (w & 1) * 32, wn = (w >> 1) * 32;                                \
    const int m0 = blockIdx.y * 64, n0 = blockIdx.x * 128;                          \
    const int lr = tid >> 1, lc = (tid & 1) * 16;                                   \
    const __half* ga = (APTR) + (size_t)(m0 + lr) * CMODEL + lc;   /* tid<128 */    \
    const __half* gb = (BPTR) + (size_t)(n0 + lr) * CMODEL + lc;                    \
    /* ldmatrix per-lane source addresses (stage 0) */                              \
    const int arow = wm + (lane & 15);                                              \
    const int akof = (lane & 16) >> 1;            /* 0 or 8 halves */               \
    const int brow = wn + (lane & 7) + ((lane & 16) >> 1);                          \
    const int bkof = lane & 8;                                                      \
    const uint32_t aaddr0 = smem_u32(&As[0][arow][akof]);                           \
    const uint32_t baddr0 = smem_u32(&Bs[0][brow][bkof]);                           \
    float4 acc[2][4];                                                               \
    _Pragma("unroll")                                                               \
    for (int i = 0; i < 2; i++)                                                     \
        _Pragma("unroll")                                                           \
        for (int j = 0; j < 4; j++) acc[i][j] = make_float4(0.f, 0.f, 0.f, 0.f);    \
    if (tid < 128) { cp16(&As[0][lr][lc], ga); cp16(&As[0][lr][lc + 8], ga + 8); }  \
    cp16(&Bs[0][lr][lc], gb); cp16(&Bs[0][lr][lc + 8], gb + 8);                     \
    CP_COMMIT;                                                                      \
    for (int kt = 0; kt < 32; kt++) {                                               \
        if (kt < 31) {                                                              \
            const __half* pb = gb + (kt + 1) * 32;                                  \
            __half* sb = &Bs[(kt + 1) & 1][lr][lc];                                 \
            if (tid < 128) {                                                        \
                const __half* pa = ga + (kt + 1) * 32;                              \
                __half* sa = &As[(kt + 1) & 1][lr][lc];                             \
                cp16(sa, pa); cp16(sa + 8, pa + 8);                                 \
            }                                                                       \
            cp16(sb, pb); cp16(sb + 8, pb + 8);                                     \
            CP_COMMIT; CP_WAIT1;                                                    \
        } else { CP_WAIT0; }                                                        \
        __syncthreads();                                                            \
        const uint32_t aofs = (uint32_t)(kt & 1) * AS_BUF_BYTES;                    \
        const uint32_t bofs = (uint32_t)(kt & 1) * BS_BUF_BYTES;                    \
        _Pragma("unroll")                                                           \
        for (int ks = 0; ks < 2; ks++) {                                            \
            const uint32_t kb = ks * 32;   /* 16 halves = 32B */                    \
            uint32_t af[2][4], bt[2][4];                                            \
            _Pragma("unroll")                                                       \
            for (int mi = 0; mi < 2; mi++)                                          \
                LDSM4(af[mi], aaddr0 + aofs + kb + mi * (16 * KPAD * 2));           \
            _Pragma("unroll")                                                       \
            for (int p = 0; p < 2; p++)                                             \
                LDSM4(bt[p], baddr0 + bofs + kb + p * (16 * KPAD * 2));             \
            _Pragma("unroll")                                                       \
            for (int mi = 0; mi < 2; mi++)                                          \
                _Pragma("unroll")                                                   \
                for (int ni = 0; ni < 4; ni++)                                      \
                    mma_f16(acc[mi][ni], af[mi], &bt[ni >> 1][(ni & 1) * 2]);       \
        }                                                                           \
        __syncthreads();                                                            \
    }

// ---------------------------------------------------------------------------
// Kernel 1: QKV GEMM + bias + RoPE -> g_Q (scaled), g_K, g_Vt (transposed)
// grid (24, 128), block 256
// ---------------------------------------------------------------------------
__global__ __launch_bounds__(256, 3) void qkv_gemm_kernel(
    const float* __restrict__ bias)
{
    GEMM_MAINLOOP(g_Xh, g_Wh)

    #pragma unroll
    for (int mi = 0; mi < 2; mi++) {
        #pragma unroll
        for (int ni = 0; ni < 4; ni++) {
            float4 c = acc[mi][ni];
            const int col = n0 + wn + ni * 8 + 2 * tg;   // even
            const int which = col >> 10;                 // 0=q,1=k,2=v
            const int cc = col & 1023;
            const int h = cc >> 6;
            const int d0 = cc & 63;
            const float b0 = bias[col], b1 = bias[col + 1];
            const float invf = exp2f(-(float)d0 * ROPE_L2);
            const int r0 = m0 + wm + mi * 16 + g;
            #pragma unroll
            for (int half_i = 0; half_i < 2; half_i++) {
                const int r = r0 + half_i * 8;
                float v0 = (half_i ? c.z : c.x) + b0;
                float v1 = (half_i ? c.w : c.y) + b1;
                const int b = r >> 11;
                const int t = r & (SEQ - 1);
                const int bh = b * NHEAD + h;
                if (which == 2) {
                    const size_t vb = (size_t)bh * HDIM * SEQ;
                    g_Vt[vb + (size_t)d0 * SEQ + t]       = __float2half_rn(v0);
                    g_Vt[vb + (size_t)(d0 + 1) * SEQ + t] = __float2half_rn(v1);
                } else {
                    float s, co;
                    sincosf((float)t * invf, &s, &co);
                    float r0v = v0 * co - v1 * s;
                    float r1v = v0 * s  + v1 * co;
                    const size_t base = ((size_t)bh * SEQ + t) * HDIM + d0;
                    if (which == 0) {  // pre-scale Q by 1/sqrt(64)
                        *(uint32_t*)&g_Q[base] = packh2(r0v * 0.125f, r1v * 0.125f);
                    } else {
                        *(uint32_t*)&g_K[base] = packh2(r0v, r1v);
                    }
                }
            }
        }
    }
}

// ---------------------------------------------------------------------------
// Kernel 2: causal flash attention, fp16 m16n8k16 mma (byte-identical to R12).
// ---------------------------------------------------------------------------
#define KS_BUF_BYTES (32 * KSPAD * 2)   // 4608
#define VS_BUF_BYTES (64 * VSPAD * 2)   // 5120

__global__ __launch_bounds__(128, 4) void attn_kernel()
{
    __shared__ __half Ks[2][32][KSPAD];   // [buf][key][dim]
    __shared__ __half Vs[2][64][VSPAD];   // [buf][dim][key]

    const int tid = threadIdx.x;
    const int w = tid >> 5, lane = tid & 31, g = lane >> 2, tg = lane & 3;
    const int wq0 = w * 16;
    const int bh = blockIdx.y;
    const int q0 = ((int)gridDim.x - 1 - (int)blockIdx.x) * 64;  // heavy blocks first
    const size_t kqbase = (size_t)bh * SEQ * HDIM;   // Q/K base
    const size_t vbase  = (size_t)bh * HDIM * SEQ;   // Vt base
    const int lr0 = wq0 + g, lr1 = wq0 + g + 8;

    // ldmatrix source addresses (B-fragment pattern, stage 0)
    const int xrow = (lane & 7) + ((lane & 16) >> 1);  // 0..15
    const int xkof = lane & 8;                          // 0 or 8
    const uint32_t kaddr0 = smem_u32(&Ks[0][xrow][xkof]);
    const uint32_t vaddr0 = smem_u32(&Vs[0][xrow][xkof]);

#define ATTN_STAGE(B, S0)                                                          \
    {                                                                              \
        const int kr = tid >> 2, kc = (tid & 3) * 16;                              \
        cp16(&Ks[B][kr][kc],     g_K + kqbase + (size_t)((S0) + kr) * HDIM + kc);  \
        cp16(&Ks[B][kr][kc + 8], g_K + kqbase + (size_t)((S0) + kr) * HDIM + kc + 8);\
        const int vr = tid >> 1, vc = (tid & 1) * 16;                              \
        cp16(&Vs[B][vr][vc],     g_Vt + vbase + (size_t)vr * SEQ + (S0) + vc);     \
        cp16(&Vs[B][vr][vc + 8], g_Vt + vbase + (size_t)vr * SEQ + (S0) + vc + 8); \
        CP_COMMIT;                                                                 \
    }

    const int ntiles = q0 / 32 + 2;
    ATTN_STAGE(0, 0)
    ATTN_STAGE(1, 32)

    // Q fragments straight from gmem (fp16, pre-scaled)
    uint32_t qf[4][4];
    {
        const __half* qb = g_Q + kqbase + (size_t)q0 * HDIM;
        #pragma unroll
        for (int ks = 0; ks < 4; ks++) {
            const int kk = ks * 16;
            qf[ks][0] = U32(qb + (size_t)lr0 * HDIM + kk + 2*tg);
            qf[ks][1] = U32(qb + (size_t)lr1 * HDIM + kk + 2*tg);
            qf[ks][2] = U32(qb + (size_t)lr0 * HDIM + kk + 2*tg + 8);
            qf[ks][3] = U32(qb + (size_t)lr1 * HDIM + kk + 2*tg + 8);
        }
    }

    float4 o[8];
    #pragma unroll
    for (int ni = 0; ni < 8; ni++) o[ni] = make_float4(0.f, 0.f, 0.f, 0.f);
    float m0r = -1e30f, m1r = -1e30f, l0 = 0.f, l1 = 0.f;

    for (int it = 0; it < ntiles; it++) {
        const int s0 = it * 32;
        if (it + 1 < ntiles) { CP_WAIT1; } else { CP_WAIT0; }
        __syncthreads();
        const uint32_t kbuf = (uint32_t)(it & 1) * KS_BUF_BYTES;
        const uint32_t vbuf = (uint32_t)(it & 1) * VS_BUF_BYTES;

        // ---- S = Q * K^T (64 warp rows x 32 keys) ----
        float4 s[4];
        #pragma unroll
        for (int ni = 0; ni < 4; ni++) s[ni] = make_float4(0.f, 0.f, 0.f, 0.f);
        #pragma unroll
        for (int ks = 0; ks < 4; ks++) {
            const uint32_t kb = kbuf + ks * 32;   // 16 halves
            uint32_t kt2[2][4];
            #pragma unroll
            for (int p = 0; p < 2; p++)
                LDSM4(kt2[p], kaddr0 + kb + p * (16 * KSPAD * 2));
            #pragma unroll
            for (int ni = 0; ni < 4; ni++)
                mma_f16(s[ni], qf[ks], &kt2[ni >> 1][(ni & 1) * 2]);
        }

        // ---- causal mask (only tiles that can cross the diagonal) ----
        if (s0 + 31 > q0) {
            #pragma unroll
            for (int ni = 0; ni < 4; ni++) {
                const int c0 = s0 + ni * 8 + 2 * tg, c1 = c0 + 1;
                const int t0 = q0 + lr0, t1 = q0 + lr1;
                if (c0 > t0) s[ni].x = -1e30f;
                if (c1 > t0) s[ni].y = -1e30f;
                if (c0 > t1) s[ni].z = -1e30f;
                if (c1 > t1) s[ni].w = -1e30f;
            }
        }

        // ---- online softmax ----
        float tm0 = -1e30f, tm1 = -1e30f;
        #pragma unroll
        for (int ni = 0; ni < 4; ni++) {
            tm0 = fmaxf(tm0, fmaxf(s[ni].x, s[ni].y));
            tm1 = fmaxf(tm1, fmaxf(s[ni].z, s[ni].w));
        }
        tm0 = fmaxf(tm0, __shfl_xor_sync(0xffffffffu, tm0, 1));
        tm0 = fmaxf(tm0, __shfl_xor_sync(0xffffffffu, tm0, 2));
        tm1 = fmaxf(tm1, __shfl_xor_sync(0xffffffffu, tm1, 1));
        tm1 = fmaxf(tm1, __shfl_xor_sync(0xffffffffu, tm1, 2));

        const float mn0 = fmaxf(m0r, tm0), mn1 = fmaxf(m1r, tm1);
        const float cr0 = __expf(m0r - mn0), cr1 = __expf(m1r - mn1);
        m0r = mn0; m1r = mn1;

        float ls0 = 0.f, ls1 = 0.f;
        #pragma unroll
        for (int ni = 0; ni < 4; ni++) {
            s[ni].x = __expf(s[ni].x - mn0);
            s[ni].y = __expf(s[ni].y - mn0);
            s[ni].z = __expf(s[ni].z - mn1);
            s[ni].w = __expf(s[ni].w - mn1);
            ls0 += s[ni].x + s[ni].y;
            ls1 += s[ni].z + s[ni].w;
        }
        ls0 += __shfl_xor_sync(0xffffffffu, ls0, 1);
        ls0 += __shfl_xor_sync(0xffffffffu, ls0, 2);
        ls1 += __shfl_xor_sync(0xffffffffu, ls1, 1);
        ls1 += __shfl_xor_sync(0xffffffffu, ls1, 2);
        l0 = l0 * cr0 + ls0;
        l1 = l1 * cr1 + ls1;

        #pragma unroll
        for (int ni = 0; ni < 8; ni++) {
            o[ni].x *= cr0; o[ni].y *= cr0;
            o[ni].z *= cr1; o[ni].w *= cr1;
        }

        // ---- O += P * V : S C-frag IS the P A-frag (fp16 pack) ----
        #pragma unroll
        for (int ks2 = 0; ks2 < 2; ks2++) {
            uint32_t af[4];
            af[0] = packh2(s[2*ks2].x,     s[2*ks2].y);
            af[1] = packh2(s[2*ks2].z,     s[2*ks2].w);
            af[2] = packh2(s[2*ks2 + 1].x, s[2*ks2 + 1].y);
            af[3] = packh2(s[2*ks2 + 1].z, s[2*ks2 + 1].w);
            const uint32_t kb = vbuf + ks2 * 32;   // 16 halves
            #pragma unroll
            for (int p = 0; p < 4; p++) {
                uint32_t vt[4];
                LDSM4(vt, vaddr0 + kb + p * (16 * VSPAD * 2));
                mma_f16(o[2*p],     af, &vt[0]);
                mma_f16(o[2*p + 1], af, &vt[2]);
            }
        }

        __syncthreads();
        if (it + 2 < ntiles) ATTN_STAGE(it & 1, s0 + 64)
    }

    // ---- epilogue: normalize, write fp16 g_A ----
    const float inv0 = 1.f / l0, inv1 = 1.f / l1;
    const int b2 = bh >> 4, h = bh & 15;
    const int t0 = q0 + lr0, t1 = q0 + lr1;
    __half* d0p = g_A + ((size_t)(b2 * SEQ + t0)) * CMODEL + h * HDIM;
    __half* d1p = g_A + ((size_t)(b2 * SEQ + t1)) * CMODEL + h * HDIM;
    #pragma unroll
    for (int ni = 0; ni < 8; ni++) {
        const int c0 = ni * 8 + 2 * tg;
        *(uint32_t*)&d0p[c0] = packh2(o[ni].x * inv0, o[ni].y * inv0);
        *(uint32_t*)&d1p[c0] = packh2(o[ni].z * inv1, o[ni].w * inv1);
    }
#undef ATTN_STAGE
}

// ---------------------------------------------------------------------------
// Kernel 3: output projection + bias -> d_out (fp32)
// grid (8, 128), block 256
// ---------------------------------------------------------------------------
__global__ __launch_bounds__(256, 3) void proj_gemm_kernel(
    const float* __restrict__ bias, float* __restrict__ out)
{
    GEMM_MAINLOOP(g_A, g_Woh)

    #pragma unroll
    for (int mi = 0; mi < 2; mi++) {
        #pragma unroll
        for (int ni = 0; ni < 4; ni++) {
            float4 c = acc[mi][ni];
            const int col = n0 + wn + ni * 8 + 2 * tg;
            const float b0 = bias[col], b1 = bias[col + 1];
            const int r0 = m0 + wm + mi * 16 + g;
            out[(size_t)r0 * CMODEL + col]           = c.x + b0;
            out[(size_t)r0 * CMODEL + col + 1]       = c.y + b1;
            out[(size_t)(r0 + 8) * CMODEL + col]     = c.z + b0;
            out[(size_t)(r0 + 8) * CMODEL + col + 1] = c.w + b1;
        }
    }
}

// ---------------------------------------------------------------------------
extern "C" void kernel_launch(void* const* d_in, const int* in_sizes, int n_in,
                              void* d_out, int out_size)
{
    const float* x      = (const float*)d_in[0];
    const float* qkv_w  = (const float*)d_in[1];
    const float* qkv_b  = (const float*)d_in[2];
    const float* out_w  = (const float*)d_in[3];
    const float* out_b  = (const float*)d_in[4];
    float* out = (float*)d_out;

    __half* xh;  cudaGetSymbolAddress((void**)&xh,  g_Xh);
    __half* wh;  cudaGetSymbolAddress((void**)&wh,  g_Wh);
    __half* woh; cudaGetSymbolAddress((void**)&woh, g_Woh);

    // fp32 -> fp16 conversion of GEMM operands
    {
        const int n4x = MROWS * CMODEL / 4;          // 2097152
        const int n4q = 3 * CMODEL * CMODEL / 4;     // 786432
        const int n4o = CMODEL * CMODEL / 4;         // 262144
        cvt_half_kernel<<<(n4x + 255) / 256, 256>>>((const float4*)x, (uint2*)xh, n4x);
        cvt_half_kernel<<<(n4q + 255) / 256, 256>>>((const float4*)qkv_w, (uint2*)wh, n4q);
        cvt_half_kernel<<<(n4o + 255) / 256, 256>>>((const float4*)out_w, (uint2*)woh, n4o);
    }

    qkv_gemm_kernel<<<dim3(3*CMODEL/128, MROWS/64), 256>>>(qkv_b);
    attn_kernel<<<dim3(SEQ/64, BH), 128>>>();
    proj_gemm_kernel<<<dim3(CMODEL/128, MROWS/64), 256>>>(out_b, out);
}

// round 14
// speedup vs baseline: 1.3318x; 1.3318x over previous
#include <cuda_runtime.h>
#include <cuda_fp16.h>
#include <math.h>
#include <stdint.h>

// Problem constants
#define BATCH 4
#define SEQ   2048
#define CMODEL 1024
#define NHEAD 16
#define HDIM  64
#define BH    (BATCH*NHEAD)          // 64
#define MROWS (BATCH*SEQ)            // 8192

// ---------------------------------------------------------------------------
// Tiled+swizzled operand layout for bulk-staged GEMMs:
//   matrix [R][1024] (half) -> chunks of 128 rows x 32 cols stored contiguously
//   chunk index  = (rowblk*32 + ktile)          (8192 bytes each)
//   within chunk = r7*64 + c5*2   bytes, XOR-swizzled by ((r7>>1)&3)<<4
//   (8 consecutive rows cover all 32 banks; 16B-atom aligned)
// ---------------------------------------------------------------------------

// Scratch (allocation-free rule: __device__ globals)
__device__ __half g_Q[(size_t)BH*SEQ*HDIM];    // [bh][t][d], pre-scaled by 1/8
__device__ __half g_K[(size_t)BH*SEQ*HDIM];    // [bh][t][d]
__device__ __half g_Vt[(size_t)BH*HDIM*SEQ];   // [bh][d][t]  (transposed)
__device__ __half g_A[(size_t)MROWS*CMODEL];   // attention out, TILED layout
__device__ __half g_Xh[(size_t)MROWS*CMODEL];      // x, fp16 TILED
__device__ __half g_Wh[(size_t)3*CMODEL*CMODEL];   // qkv_w, fp16 TILED
__device__ __half g_Woh[(size_t)CMODEL*CMODEL];    // out_w, fp16 TILED

// log2(10000)/64
#define ROPE_L2 0.20762050593060493f

#define KSPAD 72   // attn K tile: 64 + 8 -> 144B row
#define VSPAD 40   // attn V tile: 32 + 8 -> 80B row

__device__ __forceinline__ void cp16(void* s, const void* g) {
    uint32_t sa = (uint32_t)__cvta_generic_to_shared(s);
    asm volatile("cp.async.cg.shared.global [%0], [%1], 16;\n" :: "r"(sa), "l"(g));
}
#define CP_COMMIT asm volatile("cp.async.commit_group;\n" ::: "memory")
#define CP_WAIT0  asm volatile("cp.async.wait_group 0;\n" ::: "memory")
#define CP_WAIT1  asm volatile("cp.async.wait_group 1;\n" ::: "memory")

#define U32(p) (*(const uint32_t*)(p))

__device__ __forceinline__ uint32_t smem_u32(const void* p) {
    return (uint32_t)__cvta_generic_to_shared(p);
}

__device__ __forceinline__ uint32_t packh2(float lo, float hi) {
    __half2 h = __floats2half2_rn(lo, hi);
    return *(uint32_t*)&h;
}

__device__ __forceinline__ void mma_f16(float4& d, const uint32_t* a, const uint32_t* b) {
    asm volatile(
        "mma.sync.aligned.m16n8k16.row.col.f32.f16.f16.f32 "
        "{%0,%1,%2,%3}, {%4,%5,%6,%7}, {%8,%9}, {%0,%1,%2,%3};\n"
        : "+f"(d.x), "+f"(d.y), "+f"(d.z), "+f"(d.w)
        : "r"(a[0]), "r"(a[1]), "r"(a[2]), "r"(a[3]), "r"(b[0]), "r"(b[1]));
}

#define LDSM4(R, ADDR) \
    asm volatile("ldmatrix.sync.aligned.m8n8.x4.shared.b16 {%0,%1,%2,%3}, [%4];" \
        : "=r"((R)[0]), "=r"((R)[1]), "=r"((R)[2]), "=r"((R)[3]) : "r"(ADDR))

#define MBARRIER_INIT(mb, n) \
    asm volatile("mbarrier.init.shared.b64 [%0], %1;" :: "r"(mb), "r"((uint32_t)(n)) : "memory")
#define MBARRIER_WAIT_PARITY(mb, par) do {                                       \
    uint32_t _mb = (mb), _p = (uint32_t)(par), _done;                            \
    asm volatile("{\n\t.reg .pred p;\n\t"                                        \
        "mbarrier.try_wait.parity.acquire.cta.shared::cta.b64 p, [%1], %2;\n\t"  \
        "selp.b32 %0, 1, 0, p;\n\t}" : "=r"(_done) : "r"(_mb), "r"(_p) : "memory"); \
    if (!_done) {                                                                \
        asm volatile("{\n\t.reg .pred P1;\n\t"                                   \
            "WAIT_LOOP_%=:\n\t"                                                  \
            "mbarrier.try_wait.parity.acquire.cta.shared::cta.b64 P1, [%0], %1, 0x989680;\n\t" \
            "@P1 bra.uni WAIT_DONE_%=;\n\t"                                      \
            "bra.uni WAIT_LOOP_%=;\n\t"                                          \
            "WAIT_DONE_%=:\n\t}" :: "r"(_mb), "r"(_p) : "memory");               \
    }                                                                            \
} while (0)

// ---------------------------------------------------------------------------
// Kernel 0: fp32 row-major -> fp16 TILED+swizzled
// one thread = 8 halves (16B). rows must be multiple of 128.
// ---------------------------------------------------------------------------
__global__ __launch_bounds__(256) void cvt_tile_kernel(
    const float4* __restrict__ in, __half* __restrict__ outp, int total8)
{
    const int idx = blockIdx.x * 256 + threadIdx.x;
    if (idx >= total8) return;
    const int r = idx >> 7;          // global row
    const int cseg = idx & 127;      // 8-half segment
    float4 v0 = in[(size_t)r * 256 + cseg * 2];
    float4 v1 = in[(size_t)r * 256 + cseg * 2 + 1];
    uint4 o;
    o.x = packh2(v0.x, v0.y);
    o.y = packh2(v0.z, v0.w);
    o.z = packh2(v1.x, v1.y);
    o.w = packh2(v1.z, v1.w);
    const int c0 = cseg * 8;
    const int mblk = r >> 7, kt = c0 >> 5;
    const int r7 = r & 127, c5 = c0 & 31;
    uint32_t byte = (uint32_t)(r7 * 64 + c5 * 2);
    byte ^= ((r7 >> 1) & 3) << 4;
    *(uint4*)((char*)outp + (size_t)(mblk * 32 + kt) * 8192 + byte) = o;
}

// ---------------------------------------------------------------------------
// Bulk-staged GEMM mainloop: C[128x128] of A[M][1024] * B[N][1024]^T (tiled).
// 256 threads, 8 warps 2(M)x4(N), warp tile 64x32 (R12 shape).
// 2-stage double buffer; 1 cp.async.bulk per matrix per tile (8KB),
// mbarrier completion; ldmatrix on swizzled 64B rows (conflict-free).
// ---------------------------------------------------------------------------
#define BULK_STAGE(B, KT) do {                                                      \
    const uint32_t _m = mb + 8u * (B);                                              \
    asm volatile("mbarrier.arrive.expect_tx.shared.b64 _, [%0], %1;"                \
                 :: "r"(_m), "r"(16384u) : "memory");                               \
    asm volatile("cp.async.bulk.shared::cta.global.mbarrier::complete_tx::bytes "   \
                 "[%0], [%1], %2, [%3];"                                            \
                 :: "r"(asb + (B) * 8192u), "l"((const char*)gA + (size_t)(KT) * 8192), \
                    "r"(8192u), "r"(_m) : "memory");                                \
    asm volatile("cp.async.bulk.shared::cta.global.mbarrier::complete_tx::bytes "   \
                 "[%0], [%1], %2, [%3];"                                            \
                 :: "r"(bsb + (B) * 8192u), "l"((const char*)gB + (size_t)(KT) * 8192), \
                    "r"(8192u), "r"(_m) : "memory");                                \
} while (0)

#define GEMM_MAINLOOP(APTR, BPTR)                                                   \
    __shared__ __half As[2][4096];                                                  \
    __shared__ __half Bs[2][4096];                                                  \
    __shared__ uint64_t mbar[2];                                                    \
    const int tid = threadIdx.x;                                                    \
    const int w = tid >> 5, lane = tid & 31, g = lane >> 2, tg = lane & 3;          \
    const int wm = (w & 1) * 64, wn = (w >> 1) * 32;                                \
    const int m0 = blockIdx.y * 128, n0 = blockIdx.x * 128;                         \
    const __half* gA = (APTR) + (size_t)blockIdx.y * 32 * 4096;                     \
    const __half* gB = (BPTR) + (size_t)blockIdx.x * 32 * 4096;                     \
    const uint32_t asb = smem_u32(&As[0][0]);                                       \
    const uint32_t bsb = smem_u32(&Bs[0][0]);                                       \
    const uint32_t mb = smem_u32(&mbar[0]);                                         \
    const int arow = wm + (lane & 15);                                              \
    const uint32_t abyte = (uint32_t)(arow * 64 + ((lane & 16) >> 1) * 2)           \
                           ^ (((arow >> 1) & 3) << 4);                              \
    const int brow = wn + (lane & 7) + ((lane & 16) >> 1);                          \
    const uint32_t bbyte = (uint32_t)(brow * 64 + (lane & 8) * 2)                   \
                           ^ (((brow >> 1) & 3) << 4);                              \
    float4 acc[4][4];                                                               \
    _Pragma("unroll")                                                               \
    for (int i = 0; i < 4; i++)                                                     \
        _Pragma("unroll")                                                           \
        for (int j = 0; j < 4; j++) acc[i][j] = make_float4(0.f, 0.f, 0.f, 0.f);    \
    if (tid == 0) { MBARRIER_INIT(mb, 1); MBARRIER_INIT(mb + 8, 1); }               \
    __syncthreads();                                                                \
    if (tid == 0) { BULK_STAGE(0, 0); BULK_STAGE(1, 1); }                           \
    int ph0 = 0, ph1 = 0;                                                           \
    for (int kt = 0; kt < 32; kt++) {                                               \
        const int b = kt & 1;                                                       \
        if (b == 0) { MBARRIER_WAIT_PARITY(mb, ph0); ph0 ^= 1; }                    \
        else        { MBARRIER_WAIT_PARITY(mb + 8, ph1); ph1 ^= 1; }                \
        const uint32_t ab = asb + (uint32_t)b * 8192u;                              \
        const uint32_t bb = bsb + (uint32_t)b * 8192u;                              \
        _Pragma("unroll")                                                           \
        for (int ks = 0; ks < 2; ks++) {                                            \
            const uint32_t kx = ks * 32;                                            \
            uint32_t af[4][4], bt[2][4];                                            \
            _Pragma("unroll")                                                       \
            for (int mi = 0; mi < 4; mi++)                                          \
                LDSM4(af[mi], ab + ((abyte ^ kx) + mi * 1024));                     \
            _Pragma("unroll")                                                       \
            for (int p = 0; p < 2; p++)                                             \
                LDSM4(bt[p], bb + ((bbyte ^ kx) + p * 1024));                       \
            _Pragma("unroll")                                                       \
            for (int mi = 0; mi < 4; mi++)                                          \
                _Pragma("unroll")                                                   \
                for (int ni = 0; ni < 4; ni++)                                      \
                    mma_f16(acc[mi][ni], af[mi], &bt[ni >> 1][(ni & 1) * 2]);       \
        }                                                                           \
        __syncthreads();                                                            \
        if (tid == 0 && kt + 2 < 32) BULK_STAGE(b, kt + 2);                         \
    }

// ---------------------------------------------------------------------------
// Kernel 1: QKV GEMM + bias + RoPE -> g_Q (scaled), g_K, g_Vt (transposed)
// grid (24, 64), block 256
// ---------------------------------------------------------------------------
__global__ __launch_bounds__(256) void qkv_gemm_kernel(
    const float* __restrict__ bias)
{
    GEMM_MAINLOOP(g_Xh, g_Wh)

    #pragma unroll
    for (int mi = 0; mi < 4; mi++) {
        #pragma unroll
        for (int ni = 0; ni < 4; ni++) {
            float4 c = acc[mi][ni];
            const int col = n0 + wn + ni * 8 + 2 * tg;   // even
            const int which = col >> 10;                 // 0=q,1=k,2=v
            const int cc = col & 1023;
            const int h = cc >> 6;
            const int d0 = cc & 63;
            const float b0 = bias[col], b1 = bias[col + 1];
            const float invf = exp2f(-(float)d0 * ROPE_L2);
            const int r0 = m0 + wm + mi * 16 + g;
            #pragma unroll
            for (int half_i = 0; half_i < 2; half_i++) {
                const int r = r0 + half_i * 8;
                float v0 = (half_i ? c.z : c.x) + b0;
                float v1 = (half_i ? c.w : c.y) + b1;
                const int b2 = r >> 11;
                const int t = r & (SEQ - 1);
                const int bh = b2 * NHEAD + h;
                if (which == 2) {
                    const size_t vb = (size_t)bh * HDIM * SEQ;
                    g_Vt[vb + (size_t)d0 * SEQ + t]       = __float2half_rn(v0);
                    g_Vt[vb + (size_t)(d0 + 1) * SEQ + t] = __float2half_rn(v1);
                } else {
                    float s, co;
                    sincosf((float)t * invf, &s, &co);
                    float r0v = v0 * co - v1 * s;
                    float r1v = v0 * s  + v1 * co;
                    const size_t base = ((size_t)bh * SEQ + t) * HDIM + d0;
                    if (which == 0) {  // pre-scale Q by 1/sqrt(64)
                        *(uint32_t*)&g_Q[base] = packh2(r0v * 0.125f, r1v * 0.125f);
                    } else {
                        *(uint32_t*)&g_K[base] = packh2(r0v, r1v);
                    }
                }
            }
        }
    }
}

// ---------------------------------------------------------------------------
// Kernel 2: causal flash attention (R12 mainloop; epilogue writes TILED g_A)
// ---------------------------------------------------------------------------
#define KS_BUF_BYTES (32 * KSPAD * 2)   // 4608
#define VS_BUF_BYTES (64 * VSPAD * 2)   // 5120

__global__ __launch_bounds__(128, 4) void attn_kernel()
{
    __shared__ __half Ks[2][32][KSPAD];   // [buf][key][dim]
    __shared__ __half Vs[2][64][VSPAD];   // [buf][dim][key]

    const int tid = threadIdx.x;
    const int w = tid >> 5, lane = tid & 31, g = lane >> 2, tg = lane & 3;
    const int wq0 = w * 16;
    const int bh = blockIdx.y;
    const int q0 = ((int)gridDim.x - 1 - (int)blockIdx.x) * 64;  // heavy blocks first
    const size_t kqbase = (size_t)bh * SEQ * HDIM;   // Q/K base
    const size_t vbase  = (size_t)bh * HDIM * SEQ;   // Vt base
    const int lr0 = wq0 + g, lr1 = wq0 + g + 8;

    // ldmatrix source addresses (B-fragment pattern, stage 0)
    const int xrow = (lane & 7) + ((lane & 16) >> 1);  // 0..15
    const int xkof = lane & 8;                          // 0 or 8
    const uint32_t kaddr0 = smem_u32(&Ks[0][xrow][xkof]);
    const uint32_t vaddr0 = smem_u32(&Vs[0][xrow][xkof]);

#define ATTN_STAGE(B, S0)                                                          \
    {                                                                              \
        const int kr = tid >> 2, kc = (tid & 3) * 16;                              \
        cp16(&Ks[B][kr][kc],     g_K + kqbase + (size_t)((S0) + kr) * HDIM + kc);  \
        cp16(&Ks[B][kr][kc + 8], g_K + kqbase + (size_t)((S0) + kr) * HDIM + kc + 8);\
        const int vr = tid >> 1, vc = (tid & 1) * 16;                              \
        cp16(&Vs[B][vr][vc],     g_Vt + vbase + (size_t)vr * SEQ + (S0) + vc);     \
        cp16(&Vs[B][vr][vc + 8], g_Vt + vbase + (size_t)vr * SEQ + (S0) + vc + 8); \
        CP_COMMIT;                                                                 \
    }

    const int ntiles = q0 / 32 + 2;
    ATTN_STAGE(0, 0)
    ATTN_STAGE(1, 32)

    // Q fragments straight from gmem (fp16, pre-scaled)
    uint32_t qf[4][4];
    {
        const __half* qb = g_Q + kqbase + (size_t)q0 * HDIM;
        #pragma unroll
        for (int ks = 0; ks < 4; ks++) {
            const int kk = ks * 16;
            qf[ks][0] = U32(qb + (size_t)lr0 * HDIM + kk + 2*tg);
            qf[ks][1] = U32(qb + (size_t)lr1 * HDIM + kk + 2*tg);
            qf[ks][2] = U32(qb + (size_t)lr0 * HDIM + kk + 2*tg + 8);
            qf[ks][3] = U32(qb + (size_t)lr1 * HDIM + kk + 2*tg + 8);
        }
    }

    float4 o[8];
    #pragma unroll
    for (int ni = 0; ni < 8; ni++) o[ni] = make_float4(0.f, 0.f, 0.f, 0.f);
    float m0r = -1e30f, m1r = -1e30f, l0 = 0.f, l1 = 0.f;

    for (int it = 0; it < ntiles; it++) {
        const int s0 = it * 32;
        if (it + 1 < ntiles) { CP_WAIT1; } else { CP_WAIT0; }
        __syncthreads();
        const uint32_t kbuf = (uint32_t)(it & 1) * KS_BUF_BYTES;
        const uint32_t vbuf = (uint32_t)(it & 1) * VS_BUF_BYTES;

        // ---- S = Q * K^T ----
        float4 s[4];
        #pragma unroll
        for (int ni = 0; ni < 4; ni++) s[ni] = make_float4(0.f, 0.f, 0.f, 0.f);
        #pragma unroll
        for (int ks = 0; ks < 4; ks++) {
            const uint32_t kb = kbuf + ks * 32;   // 16 halves
            uint32_t kt2[2][4];
            #pragma unroll
            for (int p = 0; p < 2; p++)
                LDSM4(kt2[p], kaddr0 + kb + p * (16 * KSPAD * 2));
            #pragma unroll
            for (int ni = 0; ni < 4; ni++)
                mma_f16(s[ni], qf[ks], &kt2[ni >> 1][(ni & 1) * 2]);
        }

        // ---- causal mask ----
        if (s0 + 31 > q0) {
            #pragma unroll
            for (int ni = 0; ni < 4; ni++) {
                const int c0 = s0 + ni * 8 + 2 * tg, c1 = c0 + 1;
                const int t0 = q0 + lr0, t1 = q0 + lr1;
                if (c0 > t0) s[ni].x = -1e30f;
                if (c1 > t0) s[ni].y = -1e30f;
                if (c0 > t1) s[ni].z = -1e30f;
                if (c1 > t1) s[ni].w = -1e30f;
            }
        }

        // ---- online softmax ----
        float tm0 = -1e30f, tm1 = -1e30f;
        #pragma unroll
        for (int ni = 0; ni < 4; ni++) {
            tm0 = fmaxf(tm0, fmaxf(s[ni].x, s[ni].y));
            tm1 = fmaxf(tm1, fmaxf(s[ni].z, s[ni].w));
        }
        tm0 = fmaxf(tm0, __shfl_xor_sync(0xffffffffu, tm0, 1));
        tm0 = fmaxf(tm0, __shfl_xor_sync(0xffffffffu, tm0, 2));
        tm1 = fmaxf(tm1, __shfl_xor_sync(0xffffffffu, tm1, 1));
        tm1 = fmaxf(tm1, __shfl_xor_sync(0xffffffffu, tm1, 2));

        const float mn0 = fmaxf(m0r, tm0), mn1 = fmaxf(m1r, tm1);
        const float cr0 = __expf(m0r - mn0), cr1 = __expf(m1r - mn1);
        m0r = mn0; m1r = mn1;

        float ls0 = 0.f, ls1 = 0.f;
        #pragma unroll
        for (int ni = 0; ni < 4; ni++) {
            s[ni].x = __expf(s[ni].x - mn0);
            s[ni].y = __expf(s[ni].y - mn0);
            s[ni].z = __expf(s[ni].z - mn1);
            s[ni].w = __expf(s[ni].w - mn1);
            ls0 += s[ni].x + s[ni].y;
            ls1 += s[ni].z + s[ni].w;
        }
        ls0 += __shfl_xor_sync(0xffffffffu, ls0, 1);
        ls0 += __shfl_xor_sync(0xffffffffu, ls0, 2);
        ls1 += __shfl_xor_sync(0xffffffffu, ls1, 1);
        ls1 += __shfl_xor_sync(0xffffffffu, ls1, 2);
        l0 = l0 * cr0 + ls0;
        l1 = l1 * cr1 + ls1;

        #pragma unroll
        for (int ni = 0; ni < 8; ni++) {
            o[ni].x *= cr0; o[ni].y *= cr0;
            o[ni].z *= cr1; o[ni].w *= cr1;
        }

        // ---- O += P * V ----
        #pragma unroll
        for (int ks2 = 0; ks2 < 2; ks2++) {
            uint32_t af[4];
            af[0] = packh2(s[2*ks2].x,     s[2*ks2].y);
            af[1] = packh2(s[2*ks2].z,     s[2*ks2].w);
            af[2] = packh2(s[2*ks2 + 1].x, s[2*ks2 + 1].y);
            af[3] = packh2(s[2*ks2 + 1].z, s[2*ks2 + 1].w);
            const uint32_t kb = vbuf + ks2 * 32;   // 16 halves
            #pragma unroll
            for (int p = 0; p < 4; p++) {
                uint32_t vt[4];
                LDSM4(vt, vaddr0 + kb + p * (16 * VSPAD * 2));
                mma_f16(o[2*p],     af, &vt[0]);
                mma_f16(o[2*p + 1], af, &vt[2]);
            }
        }

        __syncthreads();
        if (it + 2 < ntiles) ATTN_STAGE(it & 1, s0 + 64)
    }

    // ---- epilogue: normalize, write fp16 g_A in TILED+swizzled layout ----
    const float inv0 = 1.f / l0, inv1 = 1.f / l1;
    const int b2 = bh >> 4, h = bh & 15;
    const int tr0 = b2 * SEQ + q0 + lr0;
    const int tr1 = b2 * SEQ + q0 + lr1;
    char* abase = (char*)g_A;
    #pragma unroll
    for (int ni = 0; ni < 8; ni++) {
        const int c = h * HDIM + ni * 8 + 2 * tg;
        const int kt = c >> 5, c5 = c & 31;
        {
            const int mblk = tr0 >> 7, r7 = tr0 & 127;
            uint32_t byte = (uint32_t)(r7 * 64 + c5 * 2) ^ (((r7 >> 1) & 3) << 4);
            *(uint32_t*)(abase + (size_t)(mblk * 32 + kt) * 8192 + byte) =
                packh2(o[ni].x * inv0, o[ni].y * inv0);
        }
        {
            const int mblk = tr1 >> 7, r7 = tr1 & 127;
            uint32_t byte = (uint32_t)(r7 * 64 + c5 * 2) ^ (((r7 >> 1) & 3) << 4);
            *(uint32_t*)(abase + (size_t)(mblk * 32 + kt) * 8192 + byte) =
                packh2(o[ni].z * inv1, o[ni].w * inv1);
        }
    }
#undef ATTN_STAGE
}

// ---------------------------------------------------------------------------
// Kernel 3: output projection + bias -> d_out (fp32). grid (8, 64), block 256
// ---------------------------------------------------------------------------
__global__ __launch_bounds__(256) void proj_gemm_kernel(
    const float* __restrict__ bias, float* __restrict__ out)
{
    GEMM_MAINLOOP(g_A, g_Woh)

    #pragma unroll
    for (int mi = 0; mi < 4; mi++) {
        #pragma unroll
        for (int ni = 0; ni < 4; ni++) {
            float4 c = acc[mi][ni];
            const int col = n0 + wn + ni * 8 + 2 * tg;
            const float b0 = bias[col], b1 = bias[col + 1];
            const int r0 = m0 + wm + mi * 16 + g;
            out[(size_t)r0 * CMODEL + col]           = c.x + b0;
            out[(size_t)r0 * CMODEL + col + 1]       = c.y + b1;
            out[(size_t)(r0 + 8) * CMODEL + col]     = c.z + b0;
            out[(size_t)(r0 + 8) * CMODEL + col + 1] = c.w + b1;
        }
    }
}

// ---------------------------------------------------------------------------
extern "C" void kernel_launch(void* const* d_in, const int* in_sizes, int n_in,
                              void* d_out, int out_size)
{
    const float* x      = (const float*)d_in[0];
    const float* qkv_w  = (const float*)d_in[1];
    const float* qkv_b  = (const float*)d_in[2];
    const float* out_w  = (const float*)d_in[3];
    const float* out_b  = (const float*)d_in[4];
    float* out = (float*)d_out;

    __half* xh;  cudaGetSymbolAddress((void**)&xh,  g_Xh);
    __half* wh;  cudaGetSymbolAddress((void**)&wh,  g_Wh);
    __half* woh; cudaGetSymbolAddress((void**)&woh, g_Woh);

    // fp32 -> fp16 tiled conversion of GEMM operands
    {
        const int t8x = MROWS * 128;            // 1048576 segments of 8 halves
        const int t8q = 3 * CMODEL * 128;       // 393216
        const int t8o = CMODEL * 128;           // 131072
        cvt_tile_kernel<<<(t8x + 255) / 256, 256>>>((const float4*)x, xh, t8x);
        cvt_tile_kernel<<<(t8q + 255) / 256, 256>>>((const float4*)qkv_w, wh, t8q);
        cvt_tile_kernel<<<(t8o + 255) / 256, 256>>>((const float4*)out_w, woh, t8o);
    }

    qkv_gemm_kernel<<<dim3(3*CMODEL/128, MROWS/128), 256>>>(qkv_b);
    attn_kernel<<<dim3(SEQ/64, BH), 128>>>();
    proj_gemm_kernel<<<dim3(CMODEL/128, MROWS/128), 256>>>(out_b, out);
}

// round 15
// speedup vs baseline: 1.4481x; 1.0874x over previous
#include <cuda_runtime.h>
#include <cuda_fp16.h>
#include <math.h>
#include <stdint.h>

// Problem constants
#define BATCH 4
#define SEQ   2048
#define CMODEL 1024
#define NHEAD 16
#define HDIM  64
#define BH    (BATCH*NHEAD)          // 64
#define MROWS (BATCH*SEQ)            // 8192

// ---------------------------------------------------------------------------
// Tiled+swizzled layouts (all bulk-staged):
//  GEMM operands: 128x32-half chunks (8192B), byte = r7*64+c5*2 ^ ((r7>>1)&3)<<4
//  K: per-(bh, 32-key tile) 4KB chunk,  byte = (t&31)*128 + d*2   ^ ((t&7)<<4)
//  V: per-(bh, 32-key tile) 4KB chunk,  byte = d*64 + (t&31)*2    ^ (((d>>1)&3)<<4)
// ---------------------------------------------------------------------------

// Scratch (allocation-free rule: __device__ globals)
__device__ __half g_Q[(size_t)BH*SEQ*HDIM];    // [bh][t][d], pre-scaled by 1/8
__device__ __half g_K[(size_t)BH*SEQ*HDIM];    // chunked+swizzled (see above)
__device__ __half g_Vt[(size_t)BH*HDIM*SEQ];   // chunked+swizzled (see above)
__device__ __half g_A[(size_t)MROWS*CMODEL];   // attention out, GEMM-TILED layout
__device__ __half g_Xh[(size_t)MROWS*CMODEL];      // x, fp16 TILED
__device__ __half g_Wh[(size_t)3*CMODEL*CMODEL];   // qkv_w, fp16 TILED
__device__ __half g_Woh[(size_t)CMODEL*CMODEL];    // out_w, fp16 TILED

// log2(10000)/64
#define ROPE_L2 0.20762050593060493f

#define U32(p) (*(const uint32_t*)(p))

__device__ __forceinline__ uint32_t smem_u32(const void* p) {
    return (uint32_t)__cvta_generic_to_shared(p);
}

__device__ __forceinline__ uint32_t packh2(float lo, float hi) {
    __half2 h = __floats2half2_rn(lo, hi);
    return *(uint32_t*)&h;
}

__device__ __forceinline__ void mma_f16(float4& d, const uint32_t* a, const uint32_t* b) {
    asm volatile(
        "mma.sync.aligned.m16n8k16.row.col.f32.f16.f16.f32 "
        "{%0,%1,%2,%3}, {%4,%5,%6,%7}, {%8,%9}, {%0,%1,%2,%3};\n"
        : "+f"(d.x), "+f"(d.y), "+f"(d.z), "+f"(d.w)
        : "r"(a[0]), "r"(a[1]), "r"(a[2]), "r"(a[3]), "r"(b[0]), "r"(b[1]));
}

#define LDSM4(R, ADDR) \
    asm volatile("ldmatrix.sync.aligned.m8n8.x4.shared.b16 {%0,%1,%2,%3}, [%4];" \
        : "=r"((R)[0]), "=r"((R)[1]), "=r"((R)[2]), "=r"((R)[3]) : "r"(ADDR))

#define MBARRIER_INIT(mb, n) \
    asm volatile("mbarrier.init.shared.b64 [%0], %1;" :: "r"(mb), "r"((uint32_t)(n)) : "memory")
#define MBARRIER_WAIT_PARITY(mb, par) do {                                       \
    uint32_t _mb = (mb), _p = (uint32_t)(par), _done;                            \
    asm volatile("{\n\t.reg .pred p;\n\t"                                        \
        "mbarrier.try_wait.parity.acquire.cta.shared::cta.b64 p, [%1], %2;\n\t"  \
        "selp.b32 %0, 1, 0, p;\n\t}" : "=r"(_done) : "r"(_mb), "r"(_p) : "memory"); \
    if (!_done) {                                                                \
        asm volatile("{\n\t.reg .pred P1;\n\t"                                   \
            "WAIT_LOOP_%=:\n\t"                                                  \
            "mbarrier.try_wait.parity.acquire.cta.shared::cta.b64 P1, [%0], %1, 0x989680;\n\t" \
            "@P1 bra.uni WAIT_DONE_%=;\n\t"                                      \
            "bra.uni WAIT_LOOP_%=;\n\t"                                          \
            "WAIT_DONE_%=:\n\t}" :: "r"(_mb), "r"(_p) : "memory");               \
    }                                                                            \
} while (0)

// ---------------------------------------------------------------------------
// Kernel 0: fp32 row-major -> fp16 GEMM-TILED+swizzled
// ---------------------------------------------------------------------------
__global__ __launch_bounds__(256) void cvt_tile_kernel(
    const float4* __restrict__ in, __half* __restrict__ outp, int total8)
{
    const int idx = blockIdx.x * 256 + threadIdx.x;
    if (idx >= total8) return;
    const int r = idx >> 7;          // global row
    const int cseg = idx & 127;      // 8-half segment
    float4 v0 = in[(size_t)r * 256 + cseg * 2];
    float4 v1 = in[(size_t)r * 256 + cseg * 2 + 1];
    uint4 o;
    o.x = packh2(v0.x, v0.y);
    o.y = packh2(v0.z, v0.w);
    o.z = packh2(v1.x, v1.y);
    o.w = packh2(v1.z, v1.w);
    const int c0 = cseg * 8;
    const int mblk = r >> 7, kt = c0 >> 5;
    const int r7 = r & 127, c5 = c0 & 31;
    uint32_t byte = (uint32_t)(r7 * 64 + c5 * 2);
    byte ^= ((r7 >> 1) & 3) << 4;
    *(uint4*)((char*)outp + (size_t)(mblk * 32 + kt) * 8192 + byte) = o;
}

// ---------------------------------------------------------------------------
// Bulk-staged GEMM mainloop (byte-identical to R14).
// ---------------------------------------------------------------------------
#define BULK_STAGE(B, KT) do {                                                      \
    const uint32_t _m = mb + 8u * (B);                                              \
    asm volatile("mbarrier.arrive.expect_tx.shared.b64 _, [%0], %1;"                \
                 :: "r"(_m), "r"(16384u) : "memory");                               \
    asm volatile("cp.async.bulk.shared::cta.global.mbarrier::complete_tx::bytes "   \
                 "[%0], [%1], %2, [%3];"                                            \
                 :: "r"(asb + (B) * 8192u), "l"((const char*)gA + (size_t)(KT) * 8192), \
                    "r"(8192u), "r"(_m) : "memory");                                \
    asm volatile("cp.async.bulk.shared::cta.global.mbarrier::complete_tx::bytes "   \
                 "[%0], [%1], %2, [%3];"                                            \
                 :: "r"(bsb + (B) * 8192u), "l"((const char*)gB + (size_t)(KT) * 8192), \
                    "r"(8192u), "r"(_m) : "memory");                                \
} while (0)

#define GEMM_MAINLOOP(APTR, BPTR)                                                   \
    __shared__ __half As[2][4096];                                                  \
    __shared__ __half Bs[2][4096];                                                  \
    __shared__ uint64_t mbar[2];                                                    \
    const int tid = threadIdx.x;                                                    \
    const int w = tid >> 5, lane = tid & 31, g = lane >> 2, tg = lane & 3;          \
    const int wm = (w & 1) * 64, wn = (w >> 1) * 32;                                \
    const int m0 = blockIdx.y * 128, n0 = blockIdx.x * 128;                         \
    const __half* gA = (APTR) + (size_t)blockIdx.y * 32 * 4096;                     \
    const __half* gB = (BPTR) + (size_t)blockIdx.x * 32 * 4096;                     \
    const uint32_t asb = smem_u32(&As[0][0]);                                       \
    const uint32_t bsb = smem_u32(&Bs[0][0]);                                       \
    const uint32_t mb = smem_u32(&mbar[0]);                                         \
    const int arow = wm + (lane & 15);                                              \
    const uint32_t abyte = (uint32_t)(arow * 64 + ((lane & 16) >> 1) * 2)           \
                           ^ (((arow >> 1) & 3) << 4);                              \
    const int brow = wn + (lane & 7) + ((lane & 16) >> 1);                          \
    const uint32_t bbyte = (uint32_t)(brow * 64 + (lane & 8) * 2)                   \
                           ^ (((brow >> 1) & 3) << 4);                              \
    float4 acc[4][4];                                                               \
    _Pragma("unroll")                                                               \
    for (int i = 0; i < 4; i++)                                                     \
        _Pragma("unroll")                                                           \
        for (int j = 0; j < 4; j++) acc[i][j] = make_float4(0.f, 0.f, 0.f, 0.f);    \
    if (tid == 0) { MBARRIER_INIT(mb, 1); MBARRIER_INIT(mb + 8, 1); }               \
    __syncthreads();                                                                \
    if (tid == 0) { BULK_STAGE(0, 0); BULK_STAGE(1, 1); }                           \
    int ph0 = 0, ph1 = 0;                                                           \
    for (int kt = 0; kt < 32; kt++) {                                               \
        const int b = kt & 1;                                                       \
        if (b == 0) { MBARRIER_WAIT_PARITY(mb, ph0); ph0 ^= 1; }                    \
        else        { MBARRIER_WAIT_PARITY(mb + 8, ph1); ph1 ^= 1; }                \
        const uint32_t ab = asb + (uint32_t)b * 8192u;                              \
        const uint32_t bb = bsb + (uint32_t)b * 8192u;                              \
        _Pragma("unroll")                                                           \
        for (int ks = 0; ks < 2; ks++) {                                            \
            const uint32_t kx = ks * 32;                                            \
            uint32_t af[4][4], bt[2][4];                                            \
            _Pragma("unroll")                                                       \
            for (int mi = 0; mi < 4; mi++)                                          \
                LDSM4(af[mi], ab + ((abyte ^ kx) + mi * 1024));                     \
            _Pragma("unroll")                                                       \
            for (int p = 0; p < 2; p++)                                             \
                LDSM4(bt[p], bb + ((bbyte ^ kx) + p * 1024));                       \
            _Pragma("unroll")                                                       \
            for (int mi = 0; mi < 4; mi++)                                          \
                _Pragma("unroll")                                                   \
                for (int ni = 0; ni < 4; ni++)                                      \
                    mma_f16(acc[mi][ni], af[mi], &bt[ni >> 1][(ni & 1) * 2]);       \
        }                                                                           \
        __syncthreads();                                                            \
        if (tid == 0 && kt + 2 < 32) BULK_STAGE(b, kt + 2);                         \
    }

// ---------------------------------------------------------------------------
// Kernel 1: QKV GEMM + bias + RoPE -> g_Q, chunked g_K / g_Vt
// grid (24, 64), block 256
// ---------------------------------------------------------------------------
__global__ __launch_bounds__(256) void qkv_gemm_kernel(
    const float* __restrict__ bias)
{
    GEMM_MAINLOOP(g_Xh, g_Wh)

    #pragma unroll
    for (int mi = 0; mi < 4; mi++) {
        #pragma unroll
        for (int ni = 0; ni < 4; ni++) {
            float4 c = acc[mi][ni];
            const int col = n0 + wn + ni * 8 + 2 * tg;   // even
            const int which = col >> 10;                 // 0=q,1=k,2=v
            const int cc = col & 1023;
            const int h = cc >> 6;
            const int d0 = cc & 63;
            const float b0 = bias[col], b1 = bias[col + 1];
            const float invf = exp2f(-(float)d0 * ROPE_L2);
            const int r0 = m0 + wm + mi * 16 + g;
            #pragma unroll
            for (int half_i = 0; half_i < 2; half_i++) {
                const int r = r0 + half_i * 8;
                float v0 = (half_i ? c.z : c.x) + b0;
                float v1 = (half_i ? c.w : c.y) + b1;
                const int b2 = r >> 11;
                const int t = r & (SEQ - 1);
                const int bh = b2 * NHEAD + h;
                const int ti = t >> 5, tr = t & 31;
                if (which == 2) {
                    // V chunk: byte = d*64 + tr*2, swizzle ((d>>1)&3)<<4
                    char* vc = (char*)g_Vt + ((size_t)(bh * 64 + ti)) * 4096;
                    uint32_t bb0 = (uint32_t)(d0 * 64 + tr * 2)
                                   ^ (((d0 >> 1) & 3) << 4);
                    uint32_t bb1 = (uint32_t)((d0 + 1) * 64 + tr * 2)
                                   ^ ((((d0 + 1) >> 1) & 3) << 4);
                    *(__half*)(vc + bb0) = __float2half_rn(v0);
                    *(__half*)(vc + bb1) = __float2half_rn(v1);
                } else {
                    float s, co;
                    sincosf((float)t * invf, &s, &co);
                    float r0v = v0 * co - v1 * s;
                    float r1v = v0 * s  + v1 * co;
                    if (which == 0) {  // Q row-major, pre-scaled by 1/8
                        const size_t base = ((size_t)bh * SEQ + t) * HDIM + d0;
                        *(uint32_t*)&g_Q[base] = packh2(r0v * 0.125f, r1v * 0.125f);
                    } else {
                        // K chunk: byte = tr*128 + d*2, swizzle (tr&7)<<4
                        char* kc = (char*)g_K + ((size_t)(bh * 64 + ti)) * 4096;
                        uint32_t bbk = (uint32_t)(tr * 128 + d0 * 2)
                                       ^ ((tr & 7) << 4);
                        *(uint32_t*)(kc + bbk) = packh2(r0v, r1v);
                    }
                }
            }
        }
    }
}

// ---------------------------------------------------------------------------
// Kernel 2: causal flash attention — bulk-staged K/V chunks.
// 128 threads (4 warps); Br=64, Bc=32; double-buffered cp.async.bulk.
// ---------------------------------------------------------------------------
#define ATTN_STAGE(B, TI) do {                                                      \
    const uint32_t _m = mb + 8u * (B);                                              \
    asm volatile("mbarrier.arrive.expect_tx.shared.b64 _, [%0], %1;"                \
                 :: "r"(_m), "r"(8192u) : "memory");                                \
    asm volatile("cp.async.bulk.shared::cta.global.mbarrier::complete_tx::bytes "   \
                 "[%0], [%1], %2, [%3];"                                            \
                 :: "r"(ksb + (B) * 4096u), "l"(kcbase + (size_t)(TI) * 4096),      \
                    "r"(4096u), "r"(_m) : "memory");                                \
    asm volatile("cp.async.bulk.shared::cta.global.mbarrier::complete_tx::bytes "   \
                 "[%0], [%1], %2, [%3];"                                            \
                 :: "r"(vsb + (B) * 4096u), "l"(vcbase + (size_t)(TI) * 4096),      \
                    "r"(4096u), "r"(_m) : "memory");                                \
} while (0)

__global__ __launch_bounds__(128, 4) void attn_kernel()
{
    __shared__ __half Ks[2][2048];   // K chunk: 32 keys x 64 d (swizzled)
    __shared__ __half Vs[2][2048];   // V chunk: 64 d x 32 keys (swizzled)
    __shared__ uint64_t mbar[2];

    const int tid = threadIdx.x;
    const int w = tid >> 5, lane = tid & 31, g = lane >> 2, tg = lane & 3;
    const int wq0 = w * 16;
    const int bh = blockIdx.y;
    const int q0 = ((int)gridDim.x - 1 - (int)blockIdx.x) * 64;  // heavy blocks first
    const size_t kqbase = (size_t)bh * SEQ * HDIM;   // Q base (row-major)
    const char* kcbase = (const char*)g_K + (size_t)bh * 64 * 4096;
    const char* vcbase = (const char*)g_Vt + (size_t)bh * 64 * 4096;
    const int lr0 = wq0 + g, lr1 = wq0 + g + 8;

    const uint32_t ksb = smem_u32(&Ks[0][0]);
    const uint32_t vsb = smem_u32(&Vs[0][0]);
    const uint32_t mb = smem_u32(&mbar[0]);

    // ldmatrix lane geometry (B-fragment pattern)
    const int xr = (lane & 7) + ((lane & 16) >> 1);     // 0..15
    const uint32_t cbl = (uint32_t)(lane & 8) * 2;      // 0 or 16 bytes
    // K rows (keys): p in {0,1} -> row = xr + p*16; 128B rows, swizzle (r&7)<<4
    uint32_t krt[2], ksz[2];
    #pragma unroll
    for (int p = 0; p < 2; p++) {
        const int r = xr + p * 16;
        krt[p] = (uint32_t)r * 128;
        ksz[p] = (uint32_t)(r & 7) << 4;
    }
    // V rows (dims): p in {0..3} -> row = xr + p*16; 64B rows, swizzle ((r>>1)&3)<<4
    uint32_t vrt[4], vsz[4];
    #pragma unroll
    for (int p = 0; p < 4; p++) {
        const int r = xr + p * 16;
        vrt[p] = (uint32_t)r * 64;
        vsz[p] = (uint32_t)((r >> 1) & 3) << 4;
    }

    if (tid == 0) { MBARRIER_INIT(mb, 1); MBARRIER_INIT(mb + 8, 1); }
    __syncthreads();
    if (tid == 0) { ATTN_STAGE(0, 0); ATTN_STAGE(1, 1); }

    // Q fragments straight from gmem (fp16, pre-scaled)
    uint32_t qf[4][4];
    {
        const __half* qb = g_Q + kqbase + (size_t)q0 * HDIM;
        #pragma unroll
        for (int ks = 0; ks < 4; ks++) {
            const int kk = ks * 16;
            qf[ks][0] = U32(qb + (size_t)lr0 * HDIM + kk + 2*tg);
            qf[ks][1] = U32(qb + (size_t)lr1 * HDIM + kk + 2*tg);
            qf[ks][2] = U32(qb + (size_t)lr0 * HDIM + kk + 2*tg + 8);
            qf[ks][3] = U32(qb + (size_t)lr1 * HDIM + kk + 2*tg + 8);
        }
    }

    float4 o[8];
    #pragma unroll
    for (int ni = 0; ni < 8; ni++) o[ni] = make_float4(0.f, 0.f, 0.f, 0.f);
    float m0r = -1e30f, m1r = -1e30f, l0 = 0.f, l1 = 0.f;
    int ph0 = 0, ph1 = 0;

    const int ntiles = q0 / 32 + 2;
    for (int it = 0; it < ntiles; it++) {
        const int s0 = it * 32;
        const int b = it & 1;
        if (b == 0) { MBARRIER_WAIT_PARITY(mb, ph0); ph0 ^= 1; }
        else        { MBARRIER_WAIT_PARITY(mb + 8, ph1); ph1 ^= 1; }
        const uint32_t kb0 = ksb + (uint32_t)b * 4096u;
        const uint32_t vb0 = vsb + (uint32_t)b * 4096u;

        // ---- S = Q * K^T ----
        float4 s[4];
        #pragma unroll
        for (int ni = 0; ni < 4; ni++) s[ni] = make_float4(0.f, 0.f, 0.f, 0.f);
        #pragma unroll
        for (int ks = 0; ks < 4; ks++) {
            const uint32_t colb = cbl + ks * 32;   // < 128
            uint32_t kt2[2][4];
            #pragma unroll
            for (int p = 0; p < 2; p++)
                LDSM4(kt2[p], kb0 + krt[p] + (colb ^ ksz[p]));
            #pragma unroll
            for (int ni = 0; ni < 4; ni++)
                mma_f16(s[ni], qf[ks], &kt2[ni >> 1][(ni & 1) * 2]);
        }

        // ---- causal mask ----
        if (s0 + 31 > q0) {
            #pragma unroll
            for (int ni = 0; ni < 4; ni++) {
                const int c0 = s0 + ni * 8 + 2 * tg, c1 = c0 + 1;
                const int t0 = q0 + lr0, t1 = q0 + lr1;
                if (c0 > t0) s[ni].x = -1e30f;
                if (c1 > t0) s[ni].y = -1e30f;
                if (c0 > t1) s[ni].z = -1e30f;
                if (c1 > t1) s[ni].w = -1e30f;
            }
        }

        // ---- online softmax ----
        float tm0 = -1e30f, tm1 = -1e30f;
        #pragma unroll
        for (int ni = 0; ni < 4; ni++) {
            tm0 = fmaxf(tm0, fmaxf(s[ni].x, s[ni].y));
            tm1 = fmaxf(tm1, fmaxf(s[ni].z, s[ni].w));
        }
        tm0 = fmaxf(tm0, __shfl_xor_sync(0xffffffffu, tm0, 1));
        tm0 = fmaxf(tm0, __shfl_xor_sync(0xffffffffu, tm0, 2));
        tm1 = fmaxf(tm1, __shfl_xor_sync(0xffffffffu, tm1, 1));
        tm1 = fmaxf(tm1, __shfl_xor_sync(0xffffffffu, tm1, 2));

        const float mn0 = fmaxf(m0r, tm0), mn1 = fmaxf(m1r, tm1);
        const float cr0 = __expf(m0r - mn0), cr1 = __expf(m1r - mn1);
        m0r = mn0; m1r = mn1;

        float ls0 = 0.f, ls1 = 0.f;
        #pragma unroll
        for (int ni = 0; ni < 4; ni++) {
            s[ni].x = __expf(s[ni].x - mn0);
            s[ni].y = __expf(s[ni].y - mn0);
            s[ni].z = __expf(s[ni].z - mn1);
            s[ni].w = __expf(s[ni].w - mn1);
            ls0 += s[ni].x + s[ni].y;
            ls1 += s[ni].z + s[ni].w;
        }
        ls0 += __shfl_xor_sync(0xffffffffu, ls0, 1);
        ls0 += __shfl_xor_sync(0xffffffffu, ls0, 2);
        ls1 += __shfl_xor_sync(0xffffffffu, ls1, 1);
        ls1 += __shfl_xor_sync(0xffffffffu, ls1, 2);
        l0 = l0 * cr0 + ls0;
        l1 = l1 * cr1 + ls1;

        #pragma unroll
        for (int ni = 0; ni < 8; ni++) {
            o[ni].x *= cr0; o[ni].y *= cr0;
            o[ni].z *= cr1; o[ni].w *= cr1;
        }

        // ---- O += P * V ----
        #pragma unroll
        for (int ks2 = 0; ks2 < 2; ks2++) {
            uint32_t af[4];
            af[0] = packh2(s[2*ks2].x,     s[2*ks2].y);
            af[1] = packh2(s[2*ks2].z,     s[2*ks2].w);
            af[2] = packh2(s[2*ks2 + 1].x, s[2*ks2 + 1].y);
            af[3] = packh2(s[2*ks2 + 1].z, s[2*ks2 + 1].w);
            const uint32_t colb = cbl + ks2 * 32;   // < 64
            #pragma unroll
            for (int p = 0; p < 4; p++) {
                uint32_t vt[4];
                LDSM4(vt, vb0 + vrt[p] + (colb ^ vsz[p]));
                mma_f16(o[2*p],     af, &vt[0]);
                mma_f16(o[2*p + 1], af, &vt[2]);
            }
        }

        __syncthreads();
        if (tid == 0 && it + 2 < ntiles) ATTN_STAGE(b, it + 2);
    }

    // ---- epilogue: normalize, write fp16 g_A in GEMM-TILED layout ----
    const float inv0 = 1.f / l0, inv1 = 1.f / l1;
    const int b2 = bh >> 4, h = bh & 15;
    const int tr0 = b2 * SEQ + q0 + lr0;
    const int tr1 = b2 * SEQ + q0 + lr1;
    char* abase = (char*)g_A;
    #pragma unroll
    for (int ni = 0; ni < 8; ni++) {
        const int c = h * HDIM + ni * 8 + 2 * tg;
        const int kt = c >> 5, c5 = c & 31;
        {
            const int mblk = tr0 >> 7, r7 = tr0 & 127;
            uint32_t byte = (uint32_t)(r7 * 64 + c5 * 2) ^ (((r7 >> 1) & 3) << 4);
            *(uint32_t*)(abase + (size_t)(mblk * 32 + kt) * 8192 + byte) =
                packh2(o[ni].x * inv0, o[ni].y * inv0);
        }
        {
            const int mblk = tr1 >> 7, r7 = tr1 & 127;
            uint32_t byte = (uint32_t)(r7 * 64 + c5 * 2) ^ (((r7 >> 1) & 3) << 4);
            *(uint32_t*)(abase + (size_t)(mblk * 32 + kt) * 8192 + byte) =
                packh2(o[ni].z * inv1, o[ni].w * inv1);
        }
    }
}

// ---------------------------------------------------------------------------
// Kernel 3: output projection + bias -> d_out (fp32). grid (8, 64), block 256
// ---------------------------------------------------------------------------
__global__ __launch_bounds__(256) void proj_gemm_kernel(
    const float* __restrict__ bias, float* __restrict__ out)
{
    GEMM_MAINLOOP(g_A, g_Woh)

    #pragma unroll
    for (int mi = 0; mi < 4; mi++) {
        #pragma unroll
        for (int ni = 0; ni < 4; ni++) {
            float4 c = acc[mi][ni];
            const int col = n0 + wn + ni * 8 + 2 * tg;
            const float b0 = bias[col], b1 = bias[col + 1];
            const int r0 = m0 + wm + mi * 16 + g;
            out[(size_t)r0 * CMODEL + col]           = c.x + b0;
            out[(size_t)r0 * CMODEL + col + 1]       = c.y + b1;
            out[(size_t)(r0 + 8) * CMODEL + col]     = c.z + b0;
            out[(size_t)(r0 + 8) * CMODEL + col + 1] = c.w + b1;
        }
    }
}

// ---------------------------------------------------------------------------
extern "C" void kernel_launch(void* const* d_in, const int* in_sizes, int n_in,
                              void* d_out, int out_size)
{
    const float* x      = (const float*)d_in[0];
    const float* qkv_w  = (const float*)d_in[1];
    const float* qkv_b  = (const float*)d_in[2];
    const float* out_w  = (const float*)d_in[3];
    const float* out_b  = (const float*)d_in[4];
    float* out = (float*)d_out;

    __half* xh;  cudaGetSymbolAddress((void**)&xh,  g_Xh);
    __half* wh;  cudaGetSymbolAddress((void**)&wh,  g_Wh);
    __half* woh; cudaGetSymbolAddress((void**)&woh, g_Woh);

    // fp32 -> fp16 tiled conversion of GEMM operands
    {
        const int t8x = MROWS * 128;            // 1048576 segments of 8 halves
        const int t8q = 3 * CMODEL * 128;       // 393216
        const int t8o = CMODEL * 128;           // 131072
        cvt_tile_kernel<<<(t8x + 255) / 256, 256>>>((const float4*)x, xh, t8x);
        cvt_tile_kernel<<<(t8q + 255) / 256, 256>>>((const float4*)qkv_w, wh, t8q);
        cvt_tile_kernel<<<(t8o + 255) / 256, 256>>>((const float4*)out_w, woh, t8o);
    }

    qkv_gemm_kernel<<<dim3(3*CMODEL/128, MROWS/128), 256>>>(qkv_b);
    attn_kernel<<<dim3(SEQ/64, BH), 128>>>();
    proj_gemm_kernel<<<dim3(CMODEL/128, MROWS/128), 256>>>(out_b, out);
}

// round 16
// speedup vs baseline: 1.5602x; 1.0774x over previous
#include <cuda_runtime.h>
#include <cuda_fp16.h>
#include <math.h>
#include <stdint.h>

// Problem constants
#define BATCH 4
#define SEQ   2048
#define CMODEL 1024
#define NHEAD 16
#define HDIM  64
#define BH    (BATCH*NHEAD)          // 64
#define MROWS (BATCH*SEQ)            // 8192

// ---------------------------------------------------------------------------
// Tiled+swizzled layouts (all bulk-staged):
//  GEMM operands: 128x32-half chunks (8192B), byte = r7*64+c5*2 ^ ((r7>>1)&3)<<4
//  K: per-(bh, 32-key tile) 4KB chunk,  byte = (t&31)*128 + d*2   ^ ((t&7)<<4)
//  V: per-(bh, 32-key tile) 4KB chunk,  byte = d*64 + (t&31)*2    ^ (((d>>1)&3)<<4)
//  Adjacent kt / ti chunks are contiguous -> pairs staged with ONE bulk copy.
// ---------------------------------------------------------------------------

// Scratch (allocation-free rule: __device__ globals)
__device__ __half g_Q[(size_t)BH*SEQ*HDIM];    // [bh][t][d], pre-scaled by 1/8
__device__ __half g_K[(size_t)BH*SEQ*HDIM];    // chunked+swizzled
__device__ __half g_Vt[(size_t)BH*HDIM*SEQ];   // chunked+swizzled
__device__ __half g_A[(size_t)MROWS*CMODEL];   // attention out, GEMM-TILED layout
__device__ __half g_Xh[(size_t)MROWS*CMODEL];      // x, fp16 TILED
__device__ __half g_Wh[(size_t)3*CMODEL*CMODEL];   // qkv_w, fp16 TILED
__device__ __half g_Woh[(size_t)CMODEL*CMODEL];    // out_w, fp16 TILED
__device__ float  g_rope[(size_t)SEQ*HDIM];        // [t][2j]=cos, [t][2j+1]=sin

// log2(10000)/64
#define ROPE_L2 0.20762050593060493f

#define U32(p) (*(const uint32_t*)(p))

__device__ __forceinline__ uint32_t smem_u32(const void* p) {
    return (uint32_t)__cvta_generic_to_shared(p);
}

__device__ __forceinline__ uint32_t packh2(float lo, float hi) {
    __half2 h = __floats2half2_rn(lo, hi);
    return *(uint32_t*)&h;
}

__device__ __forceinline__ void mma_f16(float4& d, const uint32_t* a, const uint32_t* b) {
    asm volatile(
        "mma.sync.aligned.m16n8k16.row.col.f32.f16.f16.f32 "
        "{%0,%1,%2,%3}, {%4,%5,%6,%7}, {%8,%9}, {%0,%1,%2,%3};\n"
        : "+f"(d.x), "+f"(d.y), "+f"(d.z), "+f"(d.w)
        : "r"(a[0]), "r"(a[1]), "r"(a[2]), "r"(a[3]), "r"(b[0]), "r"(b[1]));
}

#define LDSM4(R, ADDR) \
    asm volatile("ldmatrix.sync.aligned.m8n8.x4.shared.b16 {%0,%1,%2,%3}, [%4];" \
        : "=r"((R)[0]), "=r"((R)[1]), "=r"((R)[2]), "=r"((R)[3]) : "r"(ADDR))

#define MBARRIER_INIT(mb, n) \
    asm volatile("mbarrier.init.shared.b64 [%0], %1;" :: "r"(mb), "r"((uint32_t)(n)) : "memory")
#define MBARRIER_WAIT_PARITY(mb, par) do {                                       \
    uint32_t _mb = (mb), _p = (uint32_t)(par), _done;                            \
    asm volatile("{\n\t.reg .pred p;\n\t"                                        \
        "mbarrier.try_wait.parity.acquire.cta.shared::cta.b64 p, [%1], %2;\n\t"  \
        "selp.b32 %0, 1, 0, p;\n\t}" : "=r"(_done) : "r"(_mb), "r"(_p) : "memory"); \
    if (!_done) {                                                                \
        asm volatile("{\n\t.reg .pred P1;\n\t"                                   \
            "WAIT_LOOP_%=:\n\t"                                                  \
            "mbarrier.try_wait.parity.acquire.cta.shared::cta.b64 P1, [%0], %1, 0x989680;\n\t" \
            "@P1 bra.uni WAIT_DONE_%=;\n\t"                                      \
            "bra.uni WAIT_LOOP_%=;\n\t"                                          \
            "WAIT_DONE_%=:\n\t}" :: "r"(_mb), "r"(_p) : "memory");               \
    }                                                                            \
} while (0)

// ---------------------------------------------------------------------------
// Kernel 0a: fp32 row-major -> fp16 GEMM-TILED+swizzled
// ---------------------------------------------------------------------------
__global__ __launch_bounds__(256) void cvt_tile_kernel(
    const float4* __restrict__ in, __half* __restrict__ outp, int total8)
{
    const int idx = blockIdx.x * 256 + threadIdx.x;
    if (idx >= total8) return;
    const int r = idx >> 7;          // global row
    const int cseg = idx & 127;      // 8-half segment
    float4 v0 = in[(size_t)r * 256 + cseg * 2];
    float4 v1 = in[(size_t)r * 256 + cseg * 2 + 1];
    uint4 o;
    o.x = packh2(v0.x, v0.y);
    o.y = packh2(v0.z, v0.w);
    o.z = packh2(v1.x, v1.y);
    o.w = packh2(v1.z, v1.w);
    const int c0 = cseg * 8;
    const int mblk = r >> 7, kt = c0 >> 5;
    const int r7 = r & 127, c5 = c0 & 31;
    uint32_t byte = (uint32_t)(r7 * 64 + c5 * 2);
    byte ^= ((r7 >> 1) & 3) << 4;
    *(uint4*)((char*)outp + (size_t)(mblk * 32 + kt) * 8192 + byte) = o;
}

// ---------------------------------------------------------------------------
// Kernel 0b: RoPE cos/sin table
// ---------------------------------------------------------------------------
__global__ __launch_bounds__(32) void rope_table_kernel()
{
    const int t = blockIdx.x;
    const int j = threadIdx.x;        // freq index 0..31
    const float invf = exp2f(-(float)(2 * j) * ROPE_L2);
    float s, c;
    sincosf((float)t * invf, &s, &c);
    g_rope[(size_t)t * HDIM + 2 * j]     = c;
    g_rope[(size_t)t * HDIM + 2 * j + 1] = s;
}

// ---------------------------------------------------------------------------
// Bulk-staged GEMM mainloop, PAIRED: 16 pairs of k-tiles, 16KB/matrix/stage.
// Dynamic smem: A[2][16KB] | B[2][16KB] | mbar.  65552 bytes.
// 1 mbarrier wait + 1 __syncthreads per PAIR (vs per tile).
// ---------------------------------------------------------------------------
#define GEMM_SMEM (65536 + 16)

#define BULK_STAGE2(B, P) do {                                                      \
    const uint32_t _m = mb + 8u * (B);                                              \
    asm volatile("mbarrier.arrive.expect_tx.shared.b64 _, [%0], %1;"                \
                 :: "r"(_m), "r"(32768u) : "memory");                               \
    asm volatile("cp.async.bulk.shared::cta.global.mbarrier::complete_tx::bytes "   \
                 "[%0], [%1], %2, [%3];"                                            \
                 :: "r"(asb + (B) * 16384u), "l"((const char*)gA + (size_t)(P) * 16384), \
                    "r"(16384u), "r"(_m) : "memory");                               \
    asm volatile("cp.async.bulk.shared::cta.global.mbarrier::complete_tx::bytes "   \
                 "[%0], [%1], %2, [%3];"                                            \
                 :: "r"(bsb + (B) * 16384u), "l"((const char*)gB + (size_t)(P) * 16384), \
                    "r"(16384u), "r"(_m) : "memory");                               \
} while (0)

#define GEMM_MAINLOOP(APTR, BPTR)                                                   \
    extern __shared__ char dsm[];                                                   \
    const uint32_t asb = smem_u32(dsm);                                             \
    const uint32_t bsb = asb + 32768u;                                              \
    const uint32_t mb  = asb + 65536u;                                              \
    const int tid = threadIdx.x;                                                    \
    const int w = tid >> 5, lane = tid & 31, g = lane >> 2, tg = lane & 3;          \
    const int wm = (w & 1) * 64, wn = (w >> 1) * 32;                                \
    const int m0 = blockIdx.y * 128, n0 = blockIdx.x * 128;                         \
    const __half* gA = (APTR) + (size_t)blockIdx.y * 32 * 4096;                     \
    const __half* gB = (BPTR) + (size_t)blockIdx.x * 32 * 4096;                     \
    const int arow = wm + (lane & 15);                                              \
    const uint32_t abyte = (uint32_t)(arow * 64 + ((lane & 16) >> 1) * 2)           \
                           ^ (((arow >> 1) & 3) << 4);                              \
    const int brow = wn + (lane & 7) + ((lane & 16) >> 1);                          \
    const uint32_t bbyte = (uint32_t)(brow * 64 + (lane & 8) * 2)                   \
                           ^ (((brow >> 1) & 3) << 4);                              \
    float4 acc[4][4];                                                               \
    _Pragma("unroll")                                                               \
    for (int i = 0; i < 4; i++)                                                     \
        _Pragma("unroll")                                                           \
        for (int j = 0; j < 4; j++) acc[i][j] = make_float4(0.f, 0.f, 0.f, 0.f);    \
    if (tid == 0) { MBARRIER_INIT(mb, 1); MBARRIER_INIT(mb + 8, 1); }               \
    __syncthreads();                                                                \
    if (tid == 0) { BULK_STAGE2(0, 0); BULK_STAGE2(1, 1); }                         \
    int ph0 = 0, ph1 = 0;                                                           \
    for (int p = 0; p < 16; p++) {                                                  \
        const int b = p & 1;                                                        \
        if (b == 0) { MBARRIER_WAIT_PARITY(mb, ph0); ph0 ^= 1; }                    \
        else        { MBARRIER_WAIT_PARITY(mb + 8, ph1); ph1 ^= 1; }                \
        _Pragma("unroll")                                                           \
        for (int hc = 0; hc < 2; hc++) {                                            \
            const uint32_t ab = asb + (uint32_t)b * 16384u + (uint32_t)hc * 8192u;  \
            const uint32_t bb = bsb + (uint32_t)b * 16384u + (uint32_t)hc * 8192u;  \
            _Pragma("unroll")                                                       \
            for (int ks = 0; ks < 2; ks++) {                                        \
                const uint32_t kx = ks * 32;                                        \
                uint32_t af[4][4], bt[2][4];                                        \
                _Pragma("unroll")                                                   \
                for (int mi = 0; mi < 4; mi++)                                      \
                    LDSM4(af[mi], ab + ((abyte ^ kx) + mi * 1024));                 \
                _Pragma("unroll")                                                   \
                for (int pq = 0; pq < 2; pq++)                                      \
                    LDSM4(bt[pq], bb + ((bbyte ^ kx) + pq * 1024));                 \
                _Pragma("unroll")                                                   \
                for (int mi = 0; mi < 4; mi++)                                      \
                    _Pragma("unroll")                                               \
                    for (int ni = 0; ni < 4; ni++)                                  \
                        mma_f16(acc[mi][ni], af[mi], &bt[ni >> 1][(ni & 1) * 2]);   \
            }                                                                       \
        }                                                                           \
        __syncthreads();                                                            \
        if (tid == 0 && p + 2 < 16) BULK_STAGE2(b, p + 2);                          \
    }

// ---------------------------------------------------------------------------
// Kernel 1: QKV GEMM + bias + RoPE(table) -> g_Q, chunked g_K / g_Vt
// grid (24, 64), block 256
// ---------------------------------------------------------------------------
__global__ __launch_bounds__(256) void qkv_gemm_kernel(
    const float* __restrict__ bias)
{
    GEMM_MAINLOOP(g_Xh, g_Wh)

    #pragma unroll
    for (int mi = 0; mi < 4; mi++) {
        #pragma unroll
        for (int ni = 0; ni < 4; ni++) {
            float4 c = acc[mi][ni];
            const int col = n0 + wn + ni * 8 + 2 * tg;   // even
            const int which = col >> 10;                 // 0=q,1=k,2=v
            const int cc = col & 1023;
            const int h = cc >> 6;
            const int d0 = cc & 63;
            const float b0 = bias[col], b1 = bias[col + 1];
            const int r0 = m0 + wm + mi * 16 + g;
            #pragma unroll
            for (int half_i = 0; half_i < 2; half_i++) {
                const int r = r0 + half_i * 8;
                float v0 = (half_i ? c.z : c.x) + b0;
                float v1 = (half_i ? c.w : c.y) + b1;
                const int b2 = r >> 11;
                const int t = r & (SEQ - 1);
                const int bh = b2 * NHEAD + h;
                const int ti = t >> 5, tr = t & 31;
                if (which == 2) {
                    char* vc = (char*)g_Vt + ((size_t)(bh * 64 + ti)) * 4096;
                    uint32_t bb0 = (uint32_t)(d0 * 64 + tr * 2)
                                   ^ (((d0 >> 1) & 3) << 4);
                    uint32_t bb1 = (uint32_t)((d0 + 1) * 64 + tr * 2)
                                   ^ ((((d0 + 1) >> 1) & 3) << 4);
                    *(__half*)(vc + bb0) = __float2half_rn(v0);
                    *(__half*)(vc + bb1) = __float2half_rn(v1);
                } else {
                    const float2 cs = *(const float2*)&g_rope[(size_t)t * HDIM + d0];
                    float r0v = v0 * cs.x - v1 * cs.y;
                    float r1v = v0 * cs.y + v1 * cs.x;
                    if (which == 0) {  // Q row-major, pre-scaled by 1/8
                        const size_t base = ((size_t)bh * SEQ + t) * HDIM + d0;
                        *(uint32_t*)&g_Q[base] = packh2(r0v * 0.125f, r1v * 0.125f);
                    } else {
                        char* kc = (char*)g_K + ((size_t)(bh * 64 + ti)) * 4096;
                        uint32_t bbk = (uint32_t)(tr * 128 + d0 * 2)
                                       ^ ((tr & 7) << 4);
                        *(uint32_t*)(kc + bbk) = packh2(r0v, r1v);
                    }
                }
            }
        }
    }
}

// ---------------------------------------------------------------------------
// Kernel 2: causal flash attention — PAIRED bulk-staged K/V (8KB per copy).
// 128 threads (4 warps); Br=64, Bc=32; ntiles always even.
// ---------------------------------------------------------------------------
#define ATTN_STAGE2(B, P) do {                                                      \
    const uint32_t _m = mb + 8u * (B);                                              \
    asm volatile("mbarrier.arrive.expect_tx.shared.b64 _, [%0], %1;"                \
                 :: "r"(_m), "r"(16384u) : "memory");                               \
    asm volatile("cp.async.bulk.shared::cta.global.mbarrier::complete_tx::bytes "   \
                 "[%0], [%1], %2, [%3];"                                            \
                 :: "r"(ksb + (B) * 8192u), "l"(kcbase + (size_t)(P) * 8192),       \
                    "r"(8192u), "r"(_m) : "memory");                                \
    asm volatile("cp.async.bulk.shared::cta.global.mbarrier::complete_tx::bytes "   \
                 "[%0], [%1], %2, [%3];"                                            \
                 :: "r"(vsb + (B) * 8192u), "l"(vcbase + (size_t)(P) * 8192),       \
                    "r"(8192u), "r"(_m) : "memory");                                \
} while (0)

__global__ __launch_bounds__(128, 4) void attn_kernel()
{
    __shared__ __half Ks[2][4096];   // 2 stages x (2 K chunks of 4KB)
    __shared__ __half Vs[2][4096];
    __shared__ uint64_t mbar[2];

    const int tid = threadIdx.x;
    const int w = tid >> 5, lane = tid & 31, g = lane >> 2, tg = lane & 3;
    const int wq0 = w * 16;
    const int bh = blockIdx.y;
    const int q0 = ((int)gridDim.x - 1 - (int)blockIdx.x) * 64;  // heavy blocks first
    const size_t kqbase = (size_t)bh * SEQ * HDIM;   // Q base (row-major)
    const char* kcbase = (const char*)g_K + (size_t)bh * 64 * 4096;
    const char* vcbase = (const char*)g_Vt + (size_t)bh * 64 * 4096;
    const int lr0 = wq0 + g, lr1 = wq0 + g + 8;

    const uint32_t ksb = smem_u32(&Ks[0][0]);
    const uint32_t vsb = smem_u32(&Vs[0][0]);
    const uint32_t mb = smem_u32(&mbar[0]);

    // ldmatrix lane geometry (B-fragment pattern)
    const int xr = (lane & 7) + ((lane & 16) >> 1);     // 0..15
    const uint32_t cbl = (uint32_t)(lane & 8) * 2;      // 0 or 16 bytes
    uint32_t krt[2], ksz[2];
    #pragma unroll
    for (int p = 0; p < 2; p++) {
        const int r = xr + p * 16;
        krt[p] = (uint32_t)r * 128;
        ksz[p] = (uint32_t)(r & 7) << 4;
    }
    uint32_t vrt[4], vsz[4];
    #pragma unroll
    for (int p = 0; p < 4; p++) {
        const int r = xr + p * 16;
        vrt[p] = (uint32_t)r * 64;
        vsz[p] = (uint32_t)((r >> 1) & 3) << 4;
    }

    const int ntiles = q0 / 32 + 2;      // always even
    const int npairs = ntiles >> 1;

    if (tid == 0) { MBARRIER_INIT(mb, 1); MBARRIER_INIT(mb + 8, 1); }
    __syncthreads();
    if (tid == 0) {
        ATTN_STAGE2(0, 0);
        if (npairs > 1) ATTN_STAGE2(1, 1);
    }

    // Q fragments straight from gmem (fp16, pre-scaled)
    uint32_t qf[4][4];
    {
        const __half* qb = g_Q + kqbase + (size_t)q0 * HDIM;
        #pragma unroll
        for (int ks = 0; ks < 4; ks++) {
            const int kk = ks * 16;
            qf[ks][0] = U32(qb + (size_t)lr0 * HDIM + kk + 2*tg);
            qf[ks][1] = U32(qb + (size_t)lr1 * HDIM + kk + 2*tg);
            qf[ks][2] = U32(qb + (size_t)lr0 * HDIM + kk + 2*tg + 8);
            qf[ks][3] = U32(qb + (size_t)lr1 * HDIM + kk + 2*tg + 8);
        }
    }

    float4 o[8];
    #pragma unroll
    for (int ni = 0; ni < 8; ni++) o[ni] = make_float4(0.f, 0.f, 0.f, 0.f);
    float m0r = -1e30f, m1r = -1e30f, l0 = 0.f, l1 = 0.f;
    int ph0 = 0, ph1 = 0;

    for (int pr = 0; pr < npairs; pr++) {
        const int b = pr & 1;
        if (b == 0) { MBARRIER_WAIT_PARITY(mb, ph0); ph0 ^= 1; }
        else        { MBARRIER_WAIT_PARITY(mb + 8, ph1); ph1 ^= 1; }

        #pragma unroll
        for (int sub = 0; sub < 2; sub++) {
            const int it = 2 * pr + sub;
            const int s0 = it * 32;
            const uint32_t kb0 = ksb + (uint32_t)b * 8192u + (uint32_t)sub * 4096u;
            const uint32_t vb0 = vsb + (uint32_t)b * 8192u + (uint32_t)sub * 4096u;

            // ---- S = Q * K^T ----
            float4 s[4];
            #pragma unroll
            for (int ni = 0; ni < 4; ni++) s[ni] = make_float4(0.f, 0.f, 0.f, 0.f);
            #pragma unroll
            for (int ks = 0; ks < 4; ks++) {
                const uint32_t colb = cbl + ks * 32;
                uint32_t kt2[2][4];
                #pragma unroll
                for (int p = 0; p < 2; p++)
                    LDSM4(kt2[p], kb0 + krt[p] + (colb ^ ksz[p]));
                #pragma unroll
                for (int ni = 0; ni < 4; ni++)
                    mma_f16(s[ni], qf[ks], &kt2[ni >> 1][(ni & 1) * 2]);
            }

            // ---- causal mask ----
            if (s0 + 31 > q0) {
                #pragma unroll
                for (int ni = 0; ni < 4; ni++) {
                    const int c0 = s0 + ni * 8 + 2 * tg, c1 = c0 + 1;
                    const int t0 = q0 + lr0, t1 = q0 + lr1;
                    if (c0 > t0) s[ni].x = -1e30f;
                    if (c1 > t0) s[ni].y = -1e30f;
                    if (c0 > t1) s[ni].z = -1e30f;
                    if (c1 > t1) s[ni].w = -1e30f;
                }
            }

            // ---- online softmax ----
            float tm0 = -1e30f, tm1 = -1e30f;
            #pragma unroll
            for (int ni = 0; ni < 4; ni++) {
                tm0 = fmaxf(tm0, fmaxf(s[ni].x, s[ni].y));
                tm1 = fmaxf(tm1, fmaxf(s[ni].z, s[ni].w));
            }
            tm0 = fmaxf(tm0, __shfl_xor_sync(0xffffffffu, tm0, 1));
            tm0 = fmaxf(tm0, __shfl_xor_sync(0xffffffffu, tm0, 2));
            tm1 = fmaxf(tm1, __shfl_xor_sync(0xffffffffu, tm1, 1));
            tm1 = fmaxf(tm1, __shfl_xor_sync(0xffffffffu, tm1, 2));

            const float mn0 = fmaxf(m0r, tm0), mn1 = fmaxf(m1r, tm1);
            const float cr0 = __expf(m0r - mn0), cr1 = __expf(m1r - mn1);
            m0r = mn0; m1r = mn1;

            float ls0 = 0.f, ls1 = 0.f;
            #pragma unroll
            for (int ni = 0; ni < 4; ni++) {
                s[ni].x = __expf(s[ni].x - mn0);
                s[ni].y = __expf(s[ni].y - mn0);
                s[ni].z = __expf(s[ni].z - mn1);
                s[ni].w = __expf(s[ni].w - mn1);
                ls0 += s[ni].x + s[ni].y;
                ls1 += s[ni].z + s[ni].w;
            }
            ls0 += __shfl_xor_sync(0xffffffffu, ls0, 1);
            ls0 += __shfl_xor_sync(0xffffffffu, ls0, 2);
            ls1 += __shfl_xor_sync(0xffffffffu, ls1, 1);
            ls1 += __shfl_xor_sync(0xffffffffu, ls1, 2);
            l0 = l0 * cr0 + ls0;
            l1 = l1 * cr1 + ls1;

            #pragma unroll
            for (int ni = 0; ni < 8; ni++) {
                o[ni].x *= cr0; o[ni].y *= cr0;
                o[ni].z *= cr1; o[ni].w *= cr1;
            }

            // ---- O += P * V ----
            #pragma unroll
            for (int ks2 = 0; ks2 < 2; ks2++) {
                uint32_t af[4];
                af[0] = packh2(s[2*ks2].x,     s[2*ks2].y);
                af[1] = packh2(s[2*ks2].z,     s[2*ks2].w);
                af[2] = packh2(s[2*ks2 + 1].x, s[2*ks2 + 1].y);
                af[3] = packh2(s[2*ks2 + 1].z, s[2*ks2 + 1].w);
                const uint32_t colb = cbl + ks2 * 32;
                #pragma unroll
                for (int p = 0; p < 4; p++) {
                    uint32_t vt[4];
                    LDSM4(vt, vb0 + vrt[p] + (colb ^ vsz[p]));
                    mma_f16(o[2*p],     af, &vt[0]);
                    mma_f16(o[2*p + 1], af, &vt[2]);
                }
            }
        }

        __syncthreads();
        if (tid == 0 && pr + 2 < npairs) ATTN_STAGE2(b, pr + 2);
    }

    // ---- epilogue: normalize, write fp16 g_A in GEMM-TILED layout ----
    const float inv0 = 1.f / l0, inv1 = 1.f / l1;
    const int b2 = bh >> 4, h = bh & 15;
    const int tr0 = b2 * SEQ + q0 + lr0;
    const int tr1 = b2 * SEQ + q0 + lr1;
    char* abase = (char*)g_A;
    #pragma unroll
    for (int ni = 0; ni < 8; ni++) {
        const int c = h * HDIM + ni * 8 + 2 * tg;
        const int kt = c >> 5, c5 = c & 31;
        {
            const int mblk = tr0 >> 7, r7 = tr0 & 127;
            uint32_t byte = (uint32_t)(r7 * 64 + c5 * 2) ^ (((r7 >> 1) & 3) << 4);
            *(uint32_t*)(abase + (size_t)(mblk * 32 + kt) * 8192 + byte) =
                packh2(o[ni].x * inv0, o[ni].y * inv0);
        }
        {
            const int mblk = tr1 >> 7, r7 = tr1 & 127;
            uint32_t byte = (uint32_t)(r7 * 64 + c5 * 2) ^ (((r7 >> 1) & 3) << 4);
            *(uint32_t*)(abase + (size_t)(mblk * 32 + kt) * 8192 + byte) =
                packh2(o[ni].z * inv1, o[ni].w * inv1);
        }
    }
}

// ---------------------------------------------------------------------------
// Kernel 3: output projection + bias -> d_out (fp32). grid (8, 64), block 256
// ---------------------------------------------------------------------------
__global__ __launch_bounds__(256) void proj_gemm_kernel(
    const float* __restrict__ bias, float* __restrict__ out)
{
    GEMM_MAINLOOP(g_A, g_Woh)

    #pragma unroll
    for (int mi = 0; mi < 4; mi++) {
        #pragma unroll
        for (int ni = 0; ni < 4; ni++) {
            float4 c = acc[mi][ni];
            const int col = n0 + wn + ni * 8 + 2 * tg;
            const float b0 = bias[col], b1 = bias[col + 1];
            const int r0 = m0 + wm + mi * 16 + g;
            out[(size_t)r0 * CMODEL + col]           = c.x + b0;
            out[(size_t)r0 * CMODEL + col + 1]       = c.y + b1;
            out[(size_t)(r0 + 8) * CMODEL + col]     = c.z + b0;
            out[(size_t)(r0 + 8) * CMODEL + col + 1] = c.w + b1;
        }
    }
}

// ---------------------------------------------------------------------------
extern "C" void kernel_launch(void* const* d_in, const int* in_sizes, int n_in,
                              void* d_out, int out_size)
{
    const float* x      = (const float*)d_in[0];
    const float* qkv_w  = (const float*)d_in[1];
    const float* qkv_b  = (const float*)d_in[2];
    const float* out_w  = (const float*)d_in[3];
    const float* out_b  = (const float*)d_in[4];
    float* out = (float*)d_out;

    __half* xh;  cudaGetSymbolAddress((void**)&xh,  g_Xh);
    __half* wh;  cudaGetSymbolAddress((void**)&wh,  g_Wh);
    __half* woh; cudaGetSymbolAddress((void**)&woh, g_Woh);

    cudaFuncSetAttribute(qkv_gemm_kernel,  cudaFuncAttributeMaxDynamicSharedMemorySize, GEMM_SMEM);
    cudaFuncSetAttribute(proj_gemm_kernel, cudaFuncAttributeMaxDynamicSharedMemorySize, GEMM_SMEM);

    // fp32 -> fp16 tiled conversion of GEMM operands + RoPE table
    {
        const int t8x = MROWS * 128;            // 1048576 segments of 8 halves
        const int t8q = 3 * CMODEL * 128;       // 393216
        const int t8o = CMODEL * 128;           // 131072
        cvt_tile_kernel<<<(t8x + 255) / 256, 256>>>((const float4*)x, xh, t8x);
        cvt_tile_kernel<<<(t8q + 255) / 256, 256>>>((const float4*)qkv_w, wh, t8q);
        cvt_tile_kernel<<<(t8o + 255) / 256, 256>>>((const float4*)out_w, woh, t8o);
        rope_table_kernel<<<SEQ, 32>>>();
    }

    qkv_gemm_kernel<<<dim3(3*CMODEL/128, MROWS/128), 256, GEMM_SMEM>>>(qkv_b);
    attn_kernel<<<dim3(SEQ/64, BH), 128>>>();
    proj_gemm_kernel<<<dim3(CMODEL/128, MROWS/128), 256, GEMM_SMEM>>>(out_b, out);
}